// round 1
// baseline (speedup 1.0000x reference)
#include <cuda_runtime.h>
#include <math.h>

// Problem constants
#define D_IN   1024
#define D_OUT  1024
#define SEQ    2048
#define BATCH  2
#define NHEAD  16
#define HDIM   64
#define NTOK   (BATCH * SEQ)   // 4096

// Scratch (device globals: allocation-free)
__device__ float g_q[NTOK * D_OUT];
__device__ float g_k[NTOK * D_OUT];
__device__ float g_v[NTOK * D_OUT];
__device__ float g_ctx[NTOK * D_OUT];

// ---------------------------------------------------------------------------
// QKV projection: out = x @ W^T, written directly in [B, H, S, hd] layout.
// 128x128 tile, BK=8, 256 threads, 8x8 per-thread microtile.
// grid: (N/128, M/128, 3)   z selects Wq/Wk/Wv and destination buffer.
// ---------------------------------------------------------------------------
__global__ __launch_bounds__(256) void qkv_gemm(const float* __restrict__ A,
                                                const float* __restrict__ Wq,
                                                const float* __restrict__ Wk,
                                                const float* __restrict__ Wv) {
    const float* W   = (blockIdx.z == 0) ? Wq  : (blockIdx.z == 1) ? Wk  : Wv;
    float*       out = (blockIdx.z == 0) ? g_q : (blockIdx.z == 1) ? g_k : g_v;

    __shared__ float As[8][128];
    __shared__ float Bs[8][128];

    const int t   = threadIdx.x;
    const int tx  = t & 15;
    const int ty  = t >> 4;
    const int row0 = blockIdx.y * 128;
    const int col0 = blockIdx.x * 128;
    const int lr = t >> 1;          // 0..127
    const int lc = (t & 1) * 4;     // 0 or 4

    float acc[8][8];
#pragma unroll
    for (int i = 0; i < 8; i++)
#pragma unroll
        for (int j = 0; j < 8; j++) acc[i][j] = 0.f;

    for (int k0 = 0; k0 < D_IN; k0 += 8) {
        float4 a = *(const float4*)&A[(size_t)(row0 + lr) * D_IN + k0 + lc];
        float4 w = *(const float4*)&W[(size_t)(col0 + lr) * D_IN + k0 + lc];
        As[lc + 0][lr] = a.x; As[lc + 1][lr] = a.y;
        As[lc + 2][lr] = a.z; As[lc + 3][lr] = a.w;
        Bs[lc + 0][lr] = w.x; Bs[lc + 1][lr] = w.y;
        Bs[lc + 2][lr] = w.z; Bs[lc + 3][lr] = w.w;
        __syncthreads();
#pragma unroll
        for (int kk = 0; kk < 8; kk++) {
            float ra[8], rb[8];
#pragma unroll
            for (int i = 0; i < 8; i++) ra[i] = As[kk][ty * 8 + i];
#pragma unroll
            for (int j = 0; j < 8; j++) rb[j] = Bs[kk][tx * 8 + j];
#pragma unroll
            for (int i = 0; i < 8; i++)
#pragma unroll
                for (int j = 0; j < 8; j++)
                    acc[i][j] = fmaf(ra[i], rb[j], acc[i][j]);
        }
        __syncthreads();
    }

    // Permuted store into [B, H, S, hd]
#pragma unroll
    for (int i = 0; i < 8; i++) {
        int tok = row0 + ty * 8 + i;
        int b = tok >> 11;          // / SEQ
        int s = tok & (SEQ - 1);
#pragma unroll
        for (int j = 0; j < 8; j++) {
            int f = col0 + tx * 8 + j;
            int h = f >> 6;
            int d = f & 63;
            out[(((size_t)(b * NHEAD + h) * SEQ + s) << 6) + d] = acc[i][j];
        }
    }
}

// ---------------------------------------------------------------------------
// Output projection: d_out = ctx @ Wo^T + bo   (ctx in [B,S,D] row-major)
// ---------------------------------------------------------------------------
__global__ __launch_bounds__(256) void proj_gemm(const float* __restrict__ Wo,
                                                 const float* __restrict__ bo,
                                                 float* __restrict__ Cout) {
    __shared__ float As[8][128];
    __shared__ float Bs[8][128];

    const int t   = threadIdx.x;
    const int tx  = t & 15;
    const int ty  = t >> 4;
    const int row0 = blockIdx.y * 128;
    const int col0 = blockIdx.x * 128;
    const int lr = t >> 1;
    const int lc = (t & 1) * 4;

    float acc[8][8];
#pragma unroll
    for (int i = 0; i < 8; i++)
#pragma unroll
        for (int j = 0; j < 8; j++) acc[i][j] = 0.f;

    for (int k0 = 0; k0 < D_OUT; k0 += 8) {
        float4 a = *(const float4*)&g_ctx[(size_t)(row0 + lr) * D_OUT + k0 + lc];
        float4 w = *(const float4*)&Wo[(size_t)(col0 + lr) * D_OUT + k0 + lc];
        As[lc + 0][lr] = a.x; As[lc + 1][lr] = a.y;
        As[lc + 2][lr] = a.z; As[lc + 3][lr] = a.w;
        Bs[lc + 0][lr] = w.x; Bs[lc + 1][lr] = w.y;
        Bs[lc + 2][lr] = w.z; Bs[lc + 3][lr] = w.w;
        __syncthreads();
#pragma unroll
        for (int kk = 0; kk < 8; kk++) {
            float ra[8], rb[8];
#pragma unroll
            for (int i = 0; i < 8; i++) ra[i] = As[kk][ty * 8 + i];
#pragma unroll
            for (int j = 0; j < 8; j++) rb[j] = Bs[kk][tx * 8 + j];
#pragma unroll
            for (int i = 0; i < 8; i++)
#pragma unroll
                for (int j = 0; j < 8; j++)
                    acc[i][j] = fmaf(ra[i], rb[j], acc[i][j]);
        }
        __syncthreads();
    }

#pragma unroll
    for (int i = 0; i < 8; i++) {
        int tok = row0 + ty * 8 + i;
#pragma unroll
        for (int j = 0; j < 8; j++) {
            int f = col0 + tx * 8 + j;
            Cout[(size_t)tok * D_OUT + f] = acc[i][j] + bo[f];
        }
    }
}

// ---------------------------------------------------------------------------
// Flash attention (causal), fp32. 64 q-rows per CTA, 64 kv per inner tile.
// 256 threads: 16x16 grid of 4x4 microtiles.
// Dyn smem: Qs[64][65] | Ks[64][65] (reused for P) | Vs[64][64]  = 49664 B
// grid: (SEQ/64, NHEAD, BATCH)
// ---------------------------------------------------------------------------
#define ATTN_SMEM ((64 * 65 * 2 + 64 * 64) * 4)

__global__ __launch_bounds__(256) void attn_kernel() {
    extern __shared__ float sm[];
    float* Qs = sm;               // [64][65]
    float* Ks = sm + 64 * 65;     // [64][65], later reused as P
    float* Vs = sm + 2 * 64 * 65; // [64][64]

    const int t  = threadIdx.x;
    const int tx = t & 15;
    const int ty = t >> 4;
    const int r0 = ty * 4;
    const int c0 = tx * 4;

    const int m0 = blockIdx.x * 64;
    const int h  = blockIdx.y;
    const int b  = blockIdx.z;

    const size_t head_base = ((size_t)(b * NHEAD + h)) * SEQ * HDIM;
    const float* qbase = g_q + head_base;
    const float* kbase = g_k + head_base;
    const float* vbase = g_v + head_base;

    // Load Q tile (64 x 64)
    for (int idx = t; idx < 64 * 16; idx += 256) {
        int r  = idx >> 4;
        int c4 = (idx & 15) << 2;
        float4 qv = *(const float4*)&qbase[(size_t)(m0 + r) * HDIM + c4];
        Qs[r * 65 + c4 + 0] = qv.x; Qs[r * 65 + c4 + 1] = qv.y;
        Qs[r * 65 + c4 + 2] = qv.z; Qs[r * 65 + c4 + 3] = qv.w;
    }

    float acc[4][4];
    float mI[4], lI[4];
#pragma unroll
    for (int i = 0; i < 4; i++) {
        mI[i] = -1e30f; lI[i] = 0.f;
#pragma unroll
        for (int j = 0; j < 4; j++) acc[i][j] = 0.f;
    }

    for (int n0 = 0; n0 <= m0; n0 += 64) {
        __syncthreads();  // previous iteration's PV reads done
        // Load K, V tiles
        for (int idx = t; idx < 64 * 16; idx += 256) {
            int r  = idx >> 4;
            int c4 = (idx & 15) << 2;
            float4 kv = *(const float4*)&kbase[(size_t)(n0 + r) * HDIM + c4];
            Ks[r * 65 + c4 + 0] = kv.x; Ks[r * 65 + c4 + 1] = kv.y;
            Ks[r * 65 + c4 + 2] = kv.z; Ks[r * 65 + c4 + 3] = kv.w;
            float4 vv = *(const float4*)&vbase[(size_t)(n0 + r) * HDIM + c4];
            Vs[r * 64 + c4 + 0] = vv.x; Vs[r * 64 + c4 + 1] = vv.y;
            Vs[r * 64 + c4 + 2] = vv.z; Vs[r * 64 + c4 + 3] = vv.w;
        }
        __syncthreads();

        // S = Q K^T
        float s[4][4];
#pragma unroll
        for (int i = 0; i < 4; i++)
#pragma unroll
            for (int j = 0; j < 4; j++) s[i][j] = 0.f;
#pragma unroll 8
        for (int kk = 0; kk < 64; kk++) {
            float ra[4], rb[4];
#pragma unroll
            for (int i = 0; i < 4; i++) ra[i] = Qs[(r0 + i) * 65 + kk];
#pragma unroll
            for (int j = 0; j < 4; j++) rb[j] = Ks[(c0 + j) * 65 + kk];
#pragma unroll
            for (int i = 0; i < 4; i++)
#pragma unroll
                for (int j = 0; j < 4; j++)
                    s[i][j] = fmaf(ra[i], rb[j], s[i][j]);
        }

        // Scale + causal mask (only the diagonal block can mask)
#pragma unroll
        for (int i = 0; i < 4; i++)
#pragma unroll
            for (int j = 0; j < 4; j++) {
                s[i][j] *= 0.125f;  // 1/sqrt(64)
                if (n0 + c0 + j > m0 + r0 + i) s[i][j] = -1e30f;
            }

        // Online softmax
        float p[4][4];
#pragma unroll
        for (int i = 0; i < 4; i++) {
            float mm = s[i][0];
#pragma unroll
            for (int j = 1; j < 4; j++) mm = fmaxf(mm, s[i][j]);
#pragma unroll
            for (int off = 8; off >= 1; off >>= 1)
                mm = fmaxf(mm, __shfl_xor_sync(0xffffffffu, mm, off));
            float mNew = fmaxf(mI[i], mm);
            float rs = 0.f;
#pragma unroll
            for (int j = 0; j < 4; j++) {
                p[i][j] = __expf(s[i][j] - mNew);
                rs += p[i][j];
            }
#pragma unroll
            for (int off = 8; off >= 1; off >>= 1)
                rs += __shfl_xor_sync(0xffffffffu, rs, off);
            float alpha = __expf(mI[i] - mNew);
            lI[i] = lI[i] * alpha + rs;
            mI[i] = mNew;
#pragma unroll
            for (int j = 0; j < 4; j++) acc[i][j] *= alpha;
        }

        __syncthreads();  // all threads done reading Ks
        // Store P into Ks's slot
#pragma unroll
        for (int i = 0; i < 4; i++)
#pragma unroll
            for (int j = 0; j < 4; j++)
                Ks[(r0 + i) * 65 + (c0 + j)] = p[i][j];
        __syncthreads();

        // O += P V
#pragma unroll 8
        for (int kv = 0; kv < 64; kv++) {
            float rp[4], rv[4];
#pragma unroll
            for (int i = 0; i < 4; i++) rp[i] = Ks[(r0 + i) * 65 + kv];
#pragma unroll
            for (int j = 0; j < 4; j++) rv[j] = Vs[kv * 64 + c0 + j];
#pragma unroll
            for (int i = 0; i < 4; i++)
#pragma unroll
                for (int j = 0; j < 4; j++)
                    acc[i][j] = fmaf(rp[i], rv[j], acc[i][j]);
        }
    }

    // Epilogue: normalize and write ctx in [B, S, H*hd]
#pragma unroll
    for (int i = 0; i < 4; i++) {
        float inv = 1.f / lI[i];
        int tok = m0 + r0 + i;
#pragma unroll
        for (int j = 0; j < 4; j++)
            g_ctx[((size_t)(b * SEQ + tok)) * D_OUT + h * HDIM + c0 + j] =
                acc[i][j] * inv;
    }
}

// ---------------------------------------------------------------------------
extern "C" void kernel_launch(void* const* d_in, const int* in_sizes, int n_in,
                              void* d_out, int out_size) {
    const float* x  = (const float*)d_in[0];
    const float* Wq = (const float*)d_in[1];
    const float* Wk = (const float*)d_in[2];
    const float* Wv = (const float*)d_in[3];
    const float* Wo = (const float*)d_in[4];
    const float* bo = (const float*)d_in[5];
    float* out = (float*)d_out;

    cudaFuncSetAttribute(attn_kernel,
                         cudaFuncAttributeMaxDynamicSharedMemorySize, ATTN_SMEM);

    // 1. QKV projections (fused into one grid, z = 0/1/2)
    qkv_gemm<<<dim3(D_OUT / 128, NTOK / 128, 3), 256>>>(x, Wq, Wk, Wv);

    // 2. Causal flash attention
    attn_kernel<<<dim3(SEQ / 64, NHEAD, BATCH), 256, ATTN_SMEM>>>();

    // 3. Output projection + bias
    proj_gemm<<<dim3(D_OUT / 128, NTOK / 128), 256>>>(Wo, bo, out);
}

// round 2
// speedup vs baseline: 2.7992x; 2.7992x over previous
#include <cuda_runtime.h>
#include <math.h>
#include <stdint.h>

#define D_IN   1024
#define D_OUT  1024
#define SEQ    2048
#define BATCH  2
#define NHEAD  16
#define HDIM   64
#define NTOK   (BATCH * SEQ)   // 4096

// Scratch: tf32 bit-patterns stored as uint32
__device__ uint32_t g_q[NTOK * D_OUT];
__device__ uint32_t g_k[NTOK * D_OUT];
__device__ uint32_t g_v[NTOK * D_OUT];
__device__ uint32_t g_ctx[NTOK * D_OUT];

__device__ __forceinline__ uint32_t f2tf(float x) {
    uint32_t u;
    asm("cvt.rna.tf32.f32 %0, %1;" : "=r"(u) : "f"(x));
    return u;
}

__device__ __forceinline__ void mma8(float c[4],
                                     uint32_t a0, uint32_t a1, uint32_t a2, uint32_t a3,
                                     uint32_t b0, uint32_t b1) {
    asm volatile(
        "mma.sync.aligned.m16n8k8.row.col.f32.tf32.tf32.f32 "
        "{%0,%1,%2,%3},{%4,%5,%6,%7},{%8,%9},{%0,%1,%2,%3};"
        : "+f"(c[0]), "+f"(c[1]), "+f"(c[2]), "+f"(c[3])
        : "r"(a0), "r"(a1), "r"(a2), "r"(a3), "r"(b0), "r"(b1));
}

// ---------------------------------------------------------------------------
// QKV projection (tf32 tensor cores): out = x @ W^T, written as tf32 bits in
// [B, H, S, hd] layout. BM=128, BN=128, BK=16, 256 threads, 8 warps (4x2).
// grid: (8, 32, 3)
// ---------------------------------------------------------------------------
__global__ __launch_bounds__(256) void qkv_gemm(const float* __restrict__ x,
                                                const float* __restrict__ Wq,
                                                const float* __restrict__ Wk,
                                                const float* __restrict__ Wv) {
    const float* W   = (blockIdx.z == 0) ? Wq  : (blockIdx.z == 1) ? Wk  : Wv;
    uint32_t*    out = (blockIdx.z == 0) ? g_q : (blockIdx.z == 1) ? g_k : g_v;

    __shared__ uint32_t As[128][20];   // [m][k], stride 20 => conflict-free frags
    __shared__ uint32_t Bs[128][20];   // [n][k]

    const int t    = threadIdx.x;
    const int lane = t & 31;
    const int wid  = t >> 5;
    const int wm   = wid & 3;          // 0..3  -> 32-row warp tile
    const int wn   = wid >> 2;         // 0..1  -> 64-col warp tile
    const int row0 = blockIdx.y * 128;
    const int col0 = blockIdx.x * 128;
    const int g    = lane >> 2;
    const int c    = lane & 3;

    float acc[2][8][4];
#pragma unroll
    for (int mi = 0; mi < 2; mi++)
#pragma unroll
        for (int ni = 0; ni < 8; ni++)
#pragma unroll
            for (int j = 0; j < 4; j++) acc[mi][ni][j] = 0.f;

    for (int k0 = 0; k0 < D_IN; k0 += 16) {
#pragma unroll
        for (int i = t; i < 512; i += 256) {
            int r  = i >> 2;
            int cc = (i & 3) << 2;
            float4 va = *(const float4*)&x[(size_t)(row0 + r) * D_IN + k0 + cc];
            As[r][cc + 0] = f2tf(va.x); As[r][cc + 1] = f2tf(va.y);
            As[r][cc + 2] = f2tf(va.z); As[r][cc + 3] = f2tf(va.w);
            float4 vb = *(const float4*)&W[(size_t)(col0 + r) * D_IN + k0 + cc];
            Bs[r][cc + 0] = f2tf(vb.x); Bs[r][cc + 1] = f2tf(vb.y);
            Bs[r][cc + 2] = f2tf(vb.z); Bs[r][cc + 3] = f2tf(vb.w);
        }
        __syncthreads();

#pragma unroll
        for (int ks = 0; ks < 16; ks += 8) {
            uint32_t af[2][4];
#pragma unroll
            for (int mi = 0; mi < 2; mi++) {
                int r = wm * 32 + mi * 16 + g;
                af[mi][0] = As[r][ks + c];
                af[mi][1] = As[r + 8][ks + c];
                af[mi][2] = As[r][ks + c + 4];
                af[mi][3] = As[r + 8][ks + c + 4];
            }
#pragma unroll
            for (int ni = 0; ni < 8; ni++) {
                int n = wn * 64 + ni * 8 + g;
                uint32_t b0 = Bs[n][ks + c];
                uint32_t b1 = Bs[n][ks + c + 4];
                mma8(acc[0][ni], af[0][0], af[0][1], af[0][2], af[0][3], b0, b1);
                mma8(acc[1][ni], af[1][0], af[1][1], af[1][2], af[1][3], b0, b1);
            }
        }
        __syncthreads();
    }

    // Epilogue: write tf32 bits in [B, H, S, hd]
    const int b = row0 >> 11;   // whole tile in one batch (128 | 2048)
#pragma unroll
    for (int mi = 0; mi < 2; mi++) {
#pragma unroll
        for (int ni = 0; ni < 8; ni++) {
            int r  = row0 + wm * 32 + mi * 16 + g;
            int f  = col0 + wn * 64 + ni * 8 + 2 * c;
            int s  = r & (SEQ - 1);
            int h  = f >> 6;
            int d  = f & 63;
            uint2 v0 = make_uint2(f2tf(acc[mi][ni][0]), f2tf(acc[mi][ni][1]));
            *(uint2*)&out[(((b * NHEAD + h) * SEQ + s) << 6) + d] = v0;
            int s2 = (r + 8) & (SEQ - 1);
            uint2 v1 = make_uint2(f2tf(acc[mi][ni][2]), f2tf(acc[mi][ni][3]));
            *(uint2*)&out[(((b * NHEAD + h) * SEQ + s2) << 6) + d] = v1;
        }
    }
}

// ---------------------------------------------------------------------------
// Output projection (tf32): d_out = ctx @ Wo^T + bo. ctx already tf32 bits.
// grid: (8, 32)
// ---------------------------------------------------------------------------
__global__ __launch_bounds__(256) void proj_gemm(const float* __restrict__ Wo,
                                                 const float* __restrict__ bo,
                                                 float* __restrict__ Cout) {
    __shared__ uint32_t As[128][20];
    __shared__ uint32_t Bs[128][20];

    const int t    = threadIdx.x;
    const int lane = t & 31;
    const int wid  = t >> 5;
    const int wm   = wid & 3;
    const int wn   = wid >> 2;
    const int row0 = blockIdx.y * 128;
    const int col0 = blockIdx.x * 128;
    const int g    = lane >> 2;
    const int c    = lane & 3;

    float acc[2][8][4];
#pragma unroll
    for (int mi = 0; mi < 2; mi++)
#pragma unroll
        for (int ni = 0; ni < 8; ni++)
#pragma unroll
            for (int j = 0; j < 4; j++) acc[mi][ni][j] = 0.f;

    for (int k0 = 0; k0 < D_OUT; k0 += 16) {
#pragma unroll
        for (int i = t; i < 512; i += 256) {
            int r  = i >> 2;
            int cc = (i & 3) << 2;
            uint4 va = *(const uint4*)&g_ctx[(size_t)(row0 + r) * D_OUT + k0 + cc];
            As[r][cc + 0] = va.x; As[r][cc + 1] = va.y;
            As[r][cc + 2] = va.z; As[r][cc + 3] = va.w;
            float4 vb = *(const float4*)&Wo[(size_t)(col0 + r) * D_OUT + k0 + cc];
            Bs[r][cc + 0] = f2tf(vb.x); Bs[r][cc + 1] = f2tf(vb.y);
            Bs[r][cc + 2] = f2tf(vb.z); Bs[r][cc + 3] = f2tf(vb.w);
        }
        __syncthreads();

#pragma unroll
        for (int ks = 0; ks < 16; ks += 8) {
            uint32_t af[2][4];
#pragma unroll
            for (int mi = 0; mi < 2; mi++) {
                int r = wm * 32 + mi * 16 + g;
                af[mi][0] = As[r][ks + c];
                af[mi][1] = As[r + 8][ks + c];
                af[mi][2] = As[r][ks + c + 4];
                af[mi][3] = As[r + 8][ks + c + 4];
            }
#pragma unroll
            for (int ni = 0; ni < 8; ni++) {
                int n = wn * 64 + ni * 8 + g;
                uint32_t b0 = Bs[n][ks + c];
                uint32_t b1 = Bs[n][ks + c + 4];
                mma8(acc[0][ni], af[0][0], af[0][1], af[0][2], af[0][3], b0, b1);
                mma8(acc[1][ni], af[1][0], af[1][1], af[1][2], af[1][3], b0, b1);
            }
        }
        __syncthreads();
    }

#pragma unroll
    for (int mi = 0; mi < 2; mi++) {
#pragma unroll
        for (int ni = 0; ni < 8; ni++) {
            int r = row0 + wm * 32 + mi * 16 + g;
            int f = col0 + wn * 64 + ni * 8 + 2 * c;
            float2 bb = make_float2(bo[f], bo[f + 1]);
            *(float2*)&Cout[(size_t)r * D_OUT + f] =
                make_float2(acc[mi][ni][0] + bb.x, acc[mi][ni][1] + bb.y);
            *(float2*)&Cout[(size_t)(r + 8) * D_OUT + f] =
                make_float2(acc[mi][ni][2] + bb.x, acc[mi][ni][3] + bb.y);
        }
    }
}

// ---------------------------------------------------------------------------
// Flash attention (causal) with tf32 tensor cores.
// 64 q-rows per CTA, 64 kv per tile. 128 threads = 4 warps, each warp 16 rows.
// Smem (dynamic): Ks[64][68] | Vs[64][68] | Ps[64][68] (uint32 tf32)
// grid: (SEQ/64, NHEAD, BATCH)
// ---------------------------------------------------------------------------
#define AS 68
#define ATTN_SMEM (3 * 64 * AS * 4)

__global__ __launch_bounds__(128) void attn_kernel() {
    extern __shared__ uint32_t smu[];
    uint32_t* Ks = smu;                 // [64][AS]  (Q staged here first)
    uint32_t* Vs = smu + 64 * AS;       // [64][AS]
    uint32_t* Ps = smu + 128 * AS;      // [64][AS]

    const int t    = threadIdx.x;
    const int lane = t & 31;
    const int w    = t >> 5;
    const int g    = lane >> 2;
    const int c    = lane & 3;

    const int m0 = blockIdx.x * 64;
    const int h  = blockIdx.y;
    const int b  = blockIdx.z;

    const size_t head_base = ((size_t)(b * NHEAD + h)) * SEQ * HDIM;
    const uint32_t* qb = g_q + head_base;
    const uint32_t* kb = g_k + head_base;
    const uint32_t* vb = g_v + head_base;

    // Stage Q in Ks, then lift fragments to registers
    for (int i = t; i < 1024; i += 128) {
        int r  = i >> 4;
        int cc = (i & 15) << 2;
        *(uint4*)&Ks[r * AS + cc] = *(const uint4*)&qb[(size_t)(m0 + r) * HDIM + cc];
    }
    __syncthreads();

    uint32_t qf[8][4];
#pragma unroll
    for (int ks = 0; ks < 8; ks++) {
        int base = (w * 16 + g) * AS + ks * 8;
        qf[ks][0] = Ks[base + c];
        qf[ks][1] = Ks[base + 8 * AS + c];
        qf[ks][2] = Ks[base + c + 4];
        qf[ks][3] = Ks[base + 8 * AS + c + 4];
    }

    float o[8][4];
#pragma unroll
    for (int ni = 0; ni < 8; ni++)
#pragma unroll
        for (int j = 0; j < 4; j++) o[ni][j] = 0.f;
    float mr0 = -1e30f, mr1 = -1e30f, lr0 = 0.f, lr1 = 0.f;

    const int rowA = m0 + w * 16 + g;     // global q-row for c0/c1
    const int rowB = rowA + 8;            // global q-row for c2/c3

    for (int n0 = 0; n0 <= m0; n0 += 64) {
        __syncthreads();   // all warps done with previous Ks/Vs (and Q frags loaded)
        for (int i = t; i < 1024; i += 128) {
            int r  = i >> 4;
            int cc = (i & 15) << 2;
            *(uint4*)&Ks[r * AS + cc] = *(const uint4*)&kb[(size_t)(n0 + r) * HDIM + cc];
            *(uint4*)&Vs[r * AS + cc] = *(const uint4*)&vb[(size_t)(n0 + r) * HDIM + cc];
        }
        __syncthreads();

        // S = Q K^T  (per-warp 16x64)
        float s[8][4];
#pragma unroll
        for (int ni = 0; ni < 8; ni++)
#pragma unroll
            for (int j = 0; j < 4; j++) s[ni][j] = 0.f;

#pragma unroll
        for (int ks = 0; ks < 8; ks++) {
#pragma unroll
            for (int ni = 0; ni < 8; ni++) {
                int n = ni * 8 + g;
                uint32_t b0 = Ks[n * AS + ks * 8 + c];
                uint32_t b1 = Ks[n * AS + ks * 8 + c + 4];
                mma8(s[ni], qf[ks][0], qf[ks][1], qf[ks][2], qf[ks][3], b0, b1);
            }
        }

        // Scale + causal mask (only the diagonal tile needs masking)
        const bool diag = (n0 == m0);
#pragma unroll
        for (int ni = 0; ni < 8; ni++) {
#pragma unroll
            for (int j = 0; j < 4; j++) s[ni][j] *= 0.125f;
            if (diag) {
                int col = n0 + ni * 8 + 2 * c;
                if (col     > rowA) s[ni][0] = -1e30f;
                if (col + 1 > rowA) s[ni][1] = -1e30f;
                if (col     > rowB) s[ni][2] = -1e30f;
                if (col + 1 > rowB) s[ni][3] = -1e30f;
            }
        }

        // Online softmax (two rows per thread; quad = full 64-col row)
        float mx0 = -1e30f, mx1 = -1e30f;
#pragma unroll
        for (int ni = 0; ni < 8; ni++) {
            mx0 = fmaxf(mx0, fmaxf(s[ni][0], s[ni][1]));
            mx1 = fmaxf(mx1, fmaxf(s[ni][2], s[ni][3]));
        }
        mx0 = fmaxf(mx0, __shfl_xor_sync(0xffffffffu, mx0, 1));
        mx0 = fmaxf(mx0, __shfl_xor_sync(0xffffffffu, mx0, 2));
        mx1 = fmaxf(mx1, __shfl_xor_sync(0xffffffffu, mx1, 1));
        mx1 = fmaxf(mx1, __shfl_xor_sync(0xffffffffu, mx1, 2));

        float mn0 = fmaxf(mr0, mx0);
        float mn1 = fmaxf(mr1, mx1);
        float sum0 = 0.f, sum1 = 0.f;
#pragma unroll
        for (int ni = 0; ni < 8; ni++) {
            s[ni][0] = __expf(s[ni][0] - mn0); sum0 += s[ni][0];
            s[ni][1] = __expf(s[ni][1] - mn0); sum0 += s[ni][1];
            s[ni][2] = __expf(s[ni][2] - mn1); sum1 += s[ni][2];
            s[ni][3] = __expf(s[ni][3] - mn1); sum1 += s[ni][3];
        }
        sum0 += __shfl_xor_sync(0xffffffffu, sum0, 1);
        sum0 += __shfl_xor_sync(0xffffffffu, sum0, 2);
        sum1 += __shfl_xor_sync(0xffffffffu, sum1, 1);
        sum1 += __shfl_xor_sync(0xffffffffu, sum1, 2);

        float a0 = __expf(mr0 - mn0);
        float a1 = __expf(mr1 - mn1);
        lr0 = lr0 * a0 + sum0;
        lr1 = lr1 * a1 + sum1;
        mr0 = mn0; mr1 = mn1;
#pragma unroll
        for (int ni = 0; ni < 8; ni++) {
            o[ni][0] *= a0; o[ni][1] *= a0;
            o[ni][2] *= a1; o[ni][3] *= a1;
        }

        // Write P (tf32) to warp-private smem rows
        int pr0 = (w * 16 + g) * AS;
#pragma unroll
        for (int ni = 0; ni < 8; ni++) {
            *(uint2*)&Ps[pr0 + ni * 8 + 2 * c] =
                make_uint2(f2tf(s[ni][0]), f2tf(s[ni][1]));
            *(uint2*)&Ps[pr0 + 8 * AS + ni * 8 + 2 * c] =
                make_uint2(f2tf(s[ni][2]), f2tf(s[ni][3]));
        }
        __syncwarp();

        // O += P V
#pragma unroll
        for (int ks = 0; ks < 8; ks++) {
            int base = (w * 16 + g) * AS + ks * 8;
            uint32_t a0f = Ps[base + c];
            uint32_t a1f = Ps[base + 8 * AS + c];
            uint32_t a2f = Ps[base + c + 4];
            uint32_t a3f = Ps[base + 8 * AS + c + 4];
#pragma unroll
            for (int ni = 0; ni < 8; ni++) {
                uint32_t b0 = Vs[(ks * 8 + c) * AS + ni * 8 + g];
                uint32_t b1 = Vs[(ks * 8 + c + 4) * AS + ni * 8 + g];
                mma8(o[ni], a0f, a1f, a2f, a3f, b0, b1);
            }
        }
    }

    // Epilogue: normalize, write ctx as tf32 in [B, S, H*hd]
    float inv0 = 1.f / lr0;
    float inv1 = 1.f / lr1;
#pragma unroll
    for (int ni = 0; ni < 8; ni++) {
        int col = h * HDIM + ni * 8 + 2 * c;
        *(uint2*)&g_ctx[((size_t)(b * SEQ + rowA)) * D_OUT + col] =
            make_uint2(f2tf(o[ni][0] * inv0), f2tf(o[ni][1] * inv0));
        *(uint2*)&g_ctx[((size_t)(b * SEQ + rowB)) * D_OUT + col] =
            make_uint2(f2tf(o[ni][2] * inv1), f2tf(o[ni][3] * inv1));
    }
}

// ---------------------------------------------------------------------------
extern "C" void kernel_launch(void* const* d_in, const int* in_sizes, int n_in,
                              void* d_out, int out_size) {
    const float* x  = (const float*)d_in[0];
    const float* Wq = (const float*)d_in[1];
    const float* Wk = (const float*)d_in[2];
    const float* Wv = (const float*)d_in[3];
    const float* Wo = (const float*)d_in[4];
    const float* bo = (const float*)d_in[5];
    float* out = (float*)d_out;

    cudaFuncSetAttribute(attn_kernel,
                         cudaFuncAttributeMaxDynamicSharedMemorySize, ATTN_SMEM);

    qkv_gemm<<<dim3(D_OUT / 128, NTOK / 128, 3), 256>>>(x, Wq, Wk, Wv);
    attn_kernel<<<dim3(SEQ / 64, NHEAD, BATCH), 128, ATTN_SMEM>>>();
    proj_gemm<<<dim3(D_OUT / 128, NTOK / 128), 256>>>(Wo, bo, out);
}

// round 5
// speedup vs baseline: 2.8552x; 1.0200x over previous
#include <cuda_runtime.h>
#include <math.h>
#include <stdint.h>

#define D_IN   1024
#define D_OUT  1024
#define SEQ    2048
#define BATCH  2
#define NHEAD  16
#define HDIM   64
#define NTOK   (BATCH * SEQ)   // 4096

// Scratch: tf32 bit-patterns stored as uint32
__device__ uint32_t g_q[NTOK * D_OUT];
__device__ uint32_t g_k[NTOK * D_OUT];
__device__ uint32_t g_v[NTOK * D_OUT];
__device__ uint32_t g_ctx[NTOK * D_OUT];

__device__ __forceinline__ uint32_t f2tf(float x) {
    uint32_t u;
    asm("cvt.rna.tf32.f32 %0, %1;" : "=r"(u) : "f"(x));
    return u;
}

__device__ __forceinline__ void mma8(float c[4],
                                     uint32_t a0, uint32_t a1, uint32_t a2, uint32_t a3,
                                     uint32_t b0, uint32_t b1) {
    asm volatile(
        "mma.sync.aligned.m16n8k8.row.col.f32.tf32.tf32.f32 "
        "{%0,%1,%2,%3},{%4,%5,%6,%7},{%8,%9},{%0,%1,%2,%3};"
        : "+f"(c[0]), "+f"(c[1]), "+f"(c[2]), "+f"(c[3])
        : "r"(a0), "r"(a1), "r"(a2), "r"(a3), "r"(b0), "r"(b1));
}

__device__ __forceinline__ void cp16(uint32_t dst_smem, const void* src) {
    asm volatile("cp.async.cg.shared.global [%0], [%1], 16;\n"
                 :: "r"(dst_smem), "l"(src));
}

// ---------------------------------------------------------------------------
// QKV projection (tf32 tensor cores, double-buffered): out = x @ W^T, written
// as tf32 bits in [B, H, S, hd] layout. BM=128, BN=128, BK=16, 256 thr.
// grid: (8, 32, 3)
// ---------------------------------------------------------------------------
__global__ __launch_bounds__(256) void qkv_gemm(const float* __restrict__ x,
                                                const float* __restrict__ Wq,
                                                const float* __restrict__ Wk,
                                                const float* __restrict__ Wv) {
    const float* W   = (blockIdx.z == 0) ? Wq  : (blockIdx.z == 1) ? Wk  : Wv;
    uint32_t*    out = (blockIdx.z == 0) ? g_q : (blockIdx.z == 1) ? g_k : g_v;

    __shared__ uint32_t As[2][128][20];   // double buffered, stride 20
    __shared__ uint32_t Bs[2][128][20];

    const int t    = threadIdx.x;
    const int lane = t & 31;
    const int wid  = t >> 5;
    const int wm   = wid & 3;
    const int wn   = wid >> 2;
    const int row0 = blockIdx.y * 128;
    const int col0 = blockIdx.x * 128;
    const int g    = lane >> 2;
    const int c    = lane & 3;
    const int r_ld  = t >> 2;          // 0..63
    const int cc_ld = (t & 3) << 2;    // 0,4,8,12

    float acc[2][8][4];
#pragma unroll
    for (int mi = 0; mi < 2; mi++)
#pragma unroll
        for (int ni = 0; ni < 8; ni++)
#pragma unroll
            for (int j = 0; j < 4; j++) acc[mi][ni][j] = 0.f;

    float4 a_st[2], b_st[2];
#define LDG_CHUNK(k0)                                                            \
    {                                                                            \
        a_st[0] = *(const float4*)&x[(size_t)(row0 + r_ld) * D_IN + (k0) + cc_ld];      \
        a_st[1] = *(const float4*)&x[(size_t)(row0 + r_ld + 64) * D_IN + (k0) + cc_ld]; \
        b_st[0] = *(const float4*)&W[(size_t)(col0 + r_ld) * D_IN + (k0) + cc_ld];      \
        b_st[1] = *(const float4*)&W[(size_t)(col0 + r_ld + 64) * D_IN + (k0) + cc_ld]; \
    }
#define STS_CHUNK(buf)                                                           \
    {                                                                            \
        *(uint4*)&As[buf][r_ld][cc_ld] =                                         \
            make_uint4(f2tf(a_st[0].x), f2tf(a_st[0].y), f2tf(a_st[0].z), f2tf(a_st[0].w)); \
        *(uint4*)&As[buf][r_ld + 64][cc_ld] =                                    \
            make_uint4(f2tf(a_st[1].x), f2tf(a_st[1].y), f2tf(a_st[1].z), f2tf(a_st[1].w)); \
        *(uint4*)&Bs[buf][r_ld][cc_ld] =                                         \
            make_uint4(f2tf(b_st[0].x), f2tf(b_st[0].y), f2tf(b_st[0].z), f2tf(b_st[0].w)); \
        *(uint4*)&Bs[buf][r_ld + 64][cc_ld] =                                    \
            make_uint4(f2tf(b_st[1].x), f2tf(b_st[1].y), f2tf(b_st[1].z), f2tf(b_st[1].w)); \
    }

    LDG_CHUNK(0);
    STS_CHUNK(0);
    __syncthreads();

    const int NC = D_IN / 16;   // 64
    for (int kc = 0; kc < NC; kc++) {
        const int cur = kc & 1;
        if (kc + 1 < NC) LDG_CHUNK((kc + 1) * 16);

#pragma unroll
        for (int ks = 0; ks < 16; ks += 8) {
            uint32_t af[2][4];
#pragma unroll
            for (int mi = 0; mi < 2; mi++) {
                int r = wm * 32 + mi * 16 + g;
                af[mi][0] = As[cur][r][ks + c];
                af[mi][1] = As[cur][r + 8][ks + c];
                af[mi][2] = As[cur][r][ks + c + 4];
                af[mi][3] = As[cur][r + 8][ks + c + 4];
            }
#pragma unroll
            for (int ni = 0; ni < 8; ni++) {
                int n = wn * 64 + ni * 8 + g;
                uint32_t b0 = Bs[cur][n][ks + c];
                uint32_t b1 = Bs[cur][n][ks + c + 4];
                mma8(acc[0][ni], af[0][0], af[0][1], af[0][2], af[0][3], b0, b1);
                mma8(acc[1][ni], af[1][0], af[1][1], af[1][2], af[1][3], b0, b1);
            }
        }
        if (kc + 1 < NC) STS_CHUNK(cur ^ 1);
        __syncthreads();
    }
#undef LDG_CHUNK
#undef STS_CHUNK

    // Epilogue: write tf32 bits in [B, H, S, hd]
    const int b = row0 >> 11;
#pragma unroll
    for (int mi = 0; mi < 2; mi++) {
#pragma unroll
        for (int ni = 0; ni < 8; ni++) {
            int r  = row0 + wm * 32 + mi * 16 + g;
            int f  = col0 + wn * 64 + ni * 8 + 2 * c;
            int s  = r & (SEQ - 1);
            int h  = f >> 6;
            int d  = f & 63;
            uint2 v0 = make_uint2(f2tf(acc[mi][ni][0]), f2tf(acc[mi][ni][1]));
            *(uint2*)&out[(((b * NHEAD + h) * SEQ + s) << 6) + d] = v0;
            int s2 = (r + 8) & (SEQ - 1);
            uint2 v1 = make_uint2(f2tf(acc[mi][ni][2]), f2tf(acc[mi][ni][3]));
            *(uint2*)&out[(((b * NHEAD + h) * SEQ + s2) << 6) + d] = v1;
        }
    }
}

// ---------------------------------------------------------------------------
// Output projection (tf32, double-buffered): d_out = ctx @ Wo^T + bo.
// ctx is already tf32 bits. grid: (8, 32)
// ---------------------------------------------------------------------------
__global__ __launch_bounds__(256) void proj_gemm(const float* __restrict__ Wo,
                                                 const float* __restrict__ bo,
                                                 float* __restrict__ Cout) {
    __shared__ uint32_t As[2][128][20];
    __shared__ uint32_t Bs[2][128][20];

    const int t    = threadIdx.x;
    const int lane = t & 31;
    const int wid  = t >> 5;
    const int wm   = wid & 3;
    const int wn   = wid >> 2;
    const int row0 = blockIdx.y * 128;
    const int col0 = blockIdx.x * 128;
    const int g    = lane >> 2;
    const int c    = lane & 3;
    const int r_ld  = t >> 2;
    const int cc_ld = (t & 3) << 2;

    float acc[2][8][4];
#pragma unroll
    for (int mi = 0; mi < 2; mi++)
#pragma unroll
        for (int ni = 0; ni < 8; ni++)
#pragma unroll
            for (int j = 0; j < 4; j++) acc[mi][ni][j] = 0.f;

    uint4  a_st[2];
    float4 b_st[2];
#define LDG_CHUNK(k0)                                                            \
    {                                                                            \
        a_st[0] = *(const uint4*)&g_ctx[(size_t)(row0 + r_ld) * D_OUT + (k0) + cc_ld];      \
        a_st[1] = *(const uint4*)&g_ctx[(size_t)(row0 + r_ld + 64) * D_OUT + (k0) + cc_ld]; \
        b_st[0] = *(const float4*)&Wo[(size_t)(col0 + r_ld) * D_IN + (k0) + cc_ld];         \
        b_st[1] = *(const float4*)&Wo[(size_t)(col0 + r_ld + 64) * D_IN + (k0) + cc_ld];    \
    }
#define STS_CHUNK(buf)                                                           \
    {                                                                            \
        *(uint4*)&As[buf][r_ld][cc_ld]      = a_st[0];                           \
        *(uint4*)&As[buf][r_ld + 64][cc_ld] = a_st[1];                           \
        *(uint4*)&Bs[buf][r_ld][cc_ld] =                                         \
            make_uint4(f2tf(b_st[0].x), f2tf(b_st[0].y), f2tf(b_st[0].z), f2tf(b_st[0].w)); \
        *(uint4*)&Bs[buf][r_ld + 64][cc_ld] =                                    \
            make_uint4(f2tf(b_st[1].x), f2tf(b_st[1].y), f2tf(b_st[1].z), f2tf(b_st[1].w)); \
    }

    LDG_CHUNK(0);
    STS_CHUNK(0);
    __syncthreads();

    const int NC = D_OUT / 16;
    for (int kc = 0; kc < NC; kc++) {
        const int cur = kc & 1;
        if (kc + 1 < NC) LDG_CHUNK((kc + 1) * 16);

#pragma unroll
        for (int ks = 0; ks < 16; ks += 8) {
            uint32_t af[2][4];
#pragma unroll
            for (int mi = 0; mi < 2; mi++) {
                int r = wm * 32 + mi * 16 + g;
                af[mi][0] = As[cur][r][ks + c];
                af[mi][1] = As[cur][r + 8][ks + c];
                af[mi][2] = As[cur][r][ks + c + 4];
                af[mi][3] = As[cur][r + 8][ks + c + 4];
            }
#pragma unroll
            for (int ni = 0; ni < 8; ni++) {
                int n = wn * 64 + ni * 8 + g;
                uint32_t b0 = Bs[cur][n][ks + c];
                uint32_t b1 = Bs[cur][n][ks + c + 4];
                mma8(acc[0][ni], af[0][0], af[0][1], af[0][2], af[0][3], b0, b1);
                mma8(acc[1][ni], af[1][0], af[1][1], af[1][2], af[1][3], b0, b1);
            }
        }
        if (kc + 1 < NC) STS_CHUNK(cur ^ 1);
        __syncthreads();
    }
#undef LDG_CHUNK
#undef STS_CHUNK

#pragma unroll
    for (int mi = 0; mi < 2; mi++) {
#pragma unroll
        for (int ni = 0; ni < 8; ni++) {
            int r = row0 + wm * 32 + mi * 16 + g;
            int f = col0 + wn * 64 + ni * 8 + 2 * c;
            float2 bb = make_float2(bo[f], bo[f + 1]);
            *(float2*)&Cout[(size_t)r * D_OUT + f] =
                make_float2(acc[mi][ni][0] + bb.x, acc[mi][ni][1] + bb.y);
            *(float2*)&Cout[(size_t)(r + 8) * D_OUT + f] =
                make_float2(acc[mi][ni][2] + bb.x, acc[mi][ni][3] + bb.y);
        }
    }
}

// ---------------------------------------------------------------------------
// Flash attention (causal), tf32 tensor cores, cp.async double-buffered K/V.
// 64 q-rows per CTA, 64 kv per tile. 128 threads = 4 warps (16 rows each).
// Smem: K0|V0|K1|V1|Ps, each [64][68] uint32.  grid: (SEQ/64, NHEAD, BATCH)
// ---------------------------------------------------------------------------
#define AS 68
#define ATTN_SMEM (5 * 64 * AS * 4)

__global__ __launch_bounds__(128) void attn_kernel() {
    extern __shared__ uint32_t smu[];
    uint32_t* Kb[2] = { smu,            smu + 2 * 64 * AS };
    uint32_t* Vb[2] = { smu + 64 * AS,  smu + 3 * 64 * AS };
    uint32_t* Ps    = smu + 4 * 64 * AS;

    const int t    = threadIdx.x;
    const int lane = t & 31;
    const int w    = t >> 5;
    const int g    = lane >> 2;
    const int c    = lane & 3;

    const int m0 = blockIdx.x * 64;
    const int h  = blockIdx.y;
    const int b  = blockIdx.z;

    const size_t head_base = ((size_t)(b * NHEAD + h)) * SEQ * HDIM;
    const uint32_t* qb = g_q + head_base;
    const uint32_t* kb = g_k + head_base;
    const uint32_t* vb = g_v + head_base;

    // Stage Q (into Ps slot), lift fragments to registers
    for (int i = t; i < 1024; i += 128) {
        int r  = i >> 4;
        int cc = (i & 15) << 2;
        *(uint4*)&Ps[r * AS + cc] = *(const uint4*)&qb[(size_t)(m0 + r) * HDIM + cc];
    }
    __syncthreads();

    uint32_t qf[8][4];
#pragma unroll
    for (int ks = 0; ks < 8; ks++) {
        int base = (w * 16 + g) * AS + ks * 8;
        qf[ks][0] = Ps[base + c];
        qf[ks][1] = Ps[base + 8 * AS + c];
        qf[ks][2] = Ps[base + c + 4];
        qf[ks][3] = Ps[base + 8 * AS + c + 4];
    }

    // cp.async addressing: each thread covers rows rl+8j (j=0..7), fixed column
    const int rl = t >> 4;             // 0..7
    const int cl = (t & 15) << 2;      // 0..60
    uint32_t kbase[2], vbase[2];
#pragma unroll
    for (int bf = 0; bf < 2; bf++) {
        kbase[bf] = (uint32_t)__cvta_generic_to_shared(&Kb[bf][rl * AS + cl]);
        vbase[bf] = (uint32_t)__cvta_generic_to_shared(&Vb[bf][rl * AS + cl]);
    }
    const size_t grow = (size_t)rl * HDIM + cl;   // element offset for row rl

#define ISSUE_TILE(n0, bf)                                                      \
    {                                                                           \
        _Pragma("unroll")                                                       \
        for (int j = 0; j < 8; j++) {                                           \
            cp16(kbase[bf] + j * (8 * AS * 4),                                  \
                 &kb[(size_t)(n0) * HDIM + grow + (size_t)j * 8 * HDIM]);       \
            cp16(vbase[bf] + j * (8 * AS * 4),                                  \
                 &vb[(size_t)(n0) * HDIM + grow + (size_t)j * 8 * HDIM]);       \
        }                                                                       \
        asm volatile("cp.async.commit_group;");                                 \
    }

    float o[8][4];
#pragma unroll
    for (int ni = 0; ni < 8; ni++)
#pragma unroll
        for (int j = 0; j < 4; j++) o[ni][j] = 0.f;
    float mr0 = -1e30f, mr1 = -1e30f, lr0 = 0.f, lr1 = 0.f;

    const int rowA = m0 + w * 16 + g;
    const int rowB = rowA + 8;
    const int NT = (m0 >> 6) + 1;

    ISSUE_TILE(0, 0);

    for (int it = 0; it < NT; it++) {
        const int n0  = it << 6;
        const int cur = it & 1;
        if (it + 1 < NT) {
            ISSUE_TILE((it + 1) << 6, cur ^ 1);
            asm volatile("cp.async.wait_group 1;");
        } else {
            asm volatile("cp.async.wait_group 0;");
        }
        __syncthreads();

        const uint32_t* Ks = Kb[cur];
        const uint32_t* Vs = Vb[cur];

        // S = Q K^T  (per-warp 16x64)
        float s[8][4];
#pragma unroll
        for (int ni = 0; ni < 8; ni++)
#pragma unroll
            for (int j = 0; j < 4; j++) s[ni][j] = 0.f;

#pragma unroll
        for (int ks = 0; ks < 8; ks++) {
#pragma unroll
            for (int ni = 0; ni < 8; ni++) {
                int n = ni * 8 + g;
                uint32_t b0 = Ks[n * AS + ks * 8 + c];
                uint32_t b1 = Ks[n * AS + ks * 8 + c + 4];
                mma8(s[ni], qf[ks][0], qf[ks][1], qf[ks][2], qf[ks][3], b0, b1);
            }
        }

        const bool diag = (n0 == m0);
#pragma unroll
        for (int ni = 0; ni < 8; ni++) {
#pragma unroll
            for (int j = 0; j < 4; j++) s[ni][j] *= 0.125f;
            if (diag) {
                int col = n0 + ni * 8 + 2 * c;
                if (col     > rowA) s[ni][0] = -1e30f;
                if (col + 1 > rowA) s[ni][1] = -1e30f;
                if (col     > rowB) s[ni][2] = -1e30f;
                if (col + 1 > rowB) s[ni][3] = -1e30f;
            }
        }

        // Online softmax
        float mx0 = -1e30f, mx1 = -1e30f;
#pragma unroll
        for (int ni = 0; ni < 8; ni++) {
            mx0 = fmaxf(mx0, fmaxf(s[ni][0], s[ni][1]));
            mx1 = fmaxf(mx1, fmaxf(s[ni][2], s[ni][3]));
        }
        mx0 = fmaxf(mx0, __shfl_xor_sync(0xffffffffu, mx0, 1));
        mx0 = fmaxf(mx0, __shfl_xor_sync(0xffffffffu, mx0, 2));
        mx1 = fmaxf(mx1, __shfl_xor_sync(0xffffffffu, mx1, 1));
        mx1 = fmaxf(mx1, __shfl_xor_sync(0xffffffffu, mx1, 2));

        float mn0 = fmaxf(mr0, mx0);
        float mn1 = fmaxf(mr1, mx1);
        float sum0 = 0.f, sum1 = 0.f;
#pragma unroll
        for (int ni = 0; ni < 8; ni++) {
            s[ni][0] = __expf(s[ni][0] - mn0); sum0 += s[ni][0];
            s[ni][1] = __expf(s[ni][1] - mn0); sum0 += s[ni][1];
            s[ni][2] = __expf(s[ni][2] - mn1); sum1 += s[ni][2];
            s[ni][3] = __expf(s[ni][3] - mn1); sum1 += s[ni][3];
        }
        sum0 += __shfl_xor_sync(0xffffffffu, sum0, 1);
        sum0 += __shfl_xor_sync(0xffffffffu, sum0, 2);
        sum1 += __shfl_xor_sync(0xffffffffu, sum1, 1);
        sum1 += __shfl_xor_sync(0xffffffffu, sum1, 2);

        float a0 = __expf(mr0 - mn0);
        float a1 = __expf(mr1 - mn1);
        lr0 = lr0 * a0 + sum0;
        lr1 = lr1 * a1 + sum1;
        mr0 = mn0; mr1 = mn1;
#pragma unroll
        for (int ni = 0; ni < 8; ni++) {
            o[ni][0] *= a0; o[ni][1] *= a0;
            o[ni][2] *= a1; o[ni][3] *= a1;
        }

        // P -> warp-private smem rows (tf32)
        int pr0 = (w * 16 + g) * AS;
#pragma unroll
        for (int ni = 0; ni < 8; ni++) {
            *(uint2*)&Ps[pr0 + ni * 8 + 2 * c] =
                make_uint2(f2tf(s[ni][0]), f2tf(s[ni][1]));
            *(uint2*)&Ps[pr0 + 8 * AS + ni * 8 + 2 * c] =
                make_uint2(f2tf(s[ni][2]), f2tf(s[ni][3]));
        }
        __syncwarp();

        // O += P V
#pragma unroll
        for (int ks = 0; ks < 8; ks++) {
            int base = (w * 16 + g) * AS + ks * 8;
            uint32_t a0f = Ps[base + c];
            uint32_t a1f = Ps[base + 8 * AS + c];
            uint32_t a2f = Ps[base + c + 4];
            uint32_t a3f = Ps[base + 8 * AS + c + 4];
#pragma unroll
            for (int ni = 0; ni < 8; ni++) {
                uint32_t b0 = Vs[(ks * 8 + c) * AS + ni * 8 + g];
                uint32_t b1 = Vs[(ks * 8 + c + 4) * AS + ni * 8 + g];
                mma8(o[ni], a0f, a1f, a2f, a3f, b0, b1);
            }
        }
        __syncthreads();   // buffer 'cur' free for reuse by next prefetch
    }
#undef ISSUE_TILE

    // Epilogue: normalize, write ctx as tf32 in [B, S, H*hd]
    float inv0 = 1.f / lr0;
    float inv1 = 1.f / lr1;
#pragma unroll
    for (int ni = 0; ni < 8; ni++) {
        int col = h * HDIM + ni * 8 + 2 * c;
        *(uint2*)&g_ctx[((size_t)(b * SEQ + rowA)) * D_OUT + col] =
            make_uint2(f2tf(o[ni][0] * inv0), f2tf(o[ni][1] * inv0));
        *(uint2*)&g_ctx[((size_t)(b * SEQ + rowB)) * D_OUT + col] =
            make_uint2(f2tf(o[ni][2] * inv1), f2tf(o[ni][3] * inv1));
    }
}

// ---------------------------------------------------------------------------
extern "C" void kernel_launch(void* const* d_in, const int* in_sizes, int n_in,
                              void* d_out, int out_size) {
    const float* x  = (const float*)d_in[0];
    const float* Wq = (const float*)d_in[1];
    const float* Wk = (const float*)d_in[2];
    const float* Wv = (const float*)d_in[3];
    const float* Wo = (const float*)d_in[4];
    const float* bo = (const float*)d_in[5];
    float* out = (float*)d_out;

    cudaFuncSetAttribute(attn_kernel,
                         cudaFuncAttributeMaxDynamicSharedMemorySize, ATTN_SMEM);

    qkv_gemm<<<dim3(D_OUT / 128, NTOK / 128, 3), 256>>>(x, Wq, Wk, Wv);
    attn_kernel<<<dim3(SEQ / 64, NHEAD, BATCH), 128, ATTN_SMEM>>>();
    proj_gemm<<<dim3(D_OUT / 128, NTOK / 128), 256>>>(Wo, bo, out);
}

// round 7
// speedup vs baseline: 3.3430x; 1.1708x over previous
#include <cuda_runtime.h>
#include <math.h>
#include <stdint.h>

#define D_IN   1024
#define D_OUT  1024
#define SEQ    2048
#define BATCH  2
#define NHEAD  16
#define HDIM   64
#define NTOK   (BATCH * SEQ)   // 4096

// Scratch (tf32 bit patterns). Q/K permuted along hd; V plain; ctx permuted
// along features; x/weights permuted along their k dim.
__device__ uint32_t g_q[NTOK * D_OUT];
__device__ uint32_t g_k[NTOK * D_OUT];
__device__ uint32_t g_v[NTOK * D_OUT];
__device__ uint32_t g_ctx[NTOK * D_OUT];
__device__ uint32_t g_xt[NTOK * D_IN];
__device__ uint32_t g_wq[D_OUT * D_IN];
__device__ uint32_t g_wk[D_OUT * D_IN];
__device__ uint32_t g_wv[D_OUT * D_IN];
__device__ uint32_t g_wo[D_OUT * D_IN];

__device__ __forceinline__ uint32_t f2tf(float x) {
    uint32_t u;
    asm("cvt.rna.tf32.f32 %0, %1;" : "=r"(u) : "f"(x));
    return u;
}

// k-permutation within groups of 8: k -> 2*(k&3) + (k>>2)
__device__ __forceinline__ int perm8(int e) { return ((e & 3) << 1) | ((e >> 2) & 1); }

__device__ __forceinline__ void mma8(float c[4],
                                     uint32_t a0, uint32_t a1, uint32_t a2, uint32_t a3,
                                     uint32_t b0, uint32_t b1) {
    asm volatile(
        "mma.sync.aligned.m16n8k8.row.col.f32.tf32.tf32.f32 "
        "{%0,%1,%2,%3},{%4,%5,%6,%7},{%8,%9},{%0,%1,%2,%3};"
        : "+f"(c[0]), "+f"(c[1]), "+f"(c[2]), "+f"(c[3])
        : "r"(a0), "r"(a1), "r"(a2), "r"(a3), "r"(b0), "r"(b1));
}

__device__ __forceinline__ void cp16(uint32_t dst_smem, const void* src) {
    asm volatile("cp.async.cg.shared.global [%0], [%1], 16;\n"
                 :: "r"(dst_smem), "l"(src));
}

// ---------------------------------------------------------------------------
// prep: convert x + 4 weight matrices to tf32 bits with k-permuted layout.
// grid: 8192 x 256 (exactly covers 2,097,152 float4 groups)
// ---------------------------------------------------------------------------
__global__ __launch_bounds__(256) void prep_kernel(const float* __restrict__ x,
                                                   const float* __restrict__ Wq,
                                                   const float* __restrict__ Wk,
                                                   const float* __restrict__ Wv,
                                                   const float* __restrict__ Wo) {
    const size_t NX4 = (size_t)NTOK * D_IN / 4;      // 1048576
    const size_t NW4 = (size_t)D_OUT * D_IN / 4;     // 262144
    size_t i4 = (size_t)blockIdx.x * 256 + threadIdx.x;

    const float* src;
    uint32_t* dst;
    size_t rel;
    if (i4 < NX4)                { src = x;  dst = g_xt; rel = i4; }
    else if (i4 < NX4 + NW4)     { src = Wq; dst = g_wq; rel = i4 - NX4; }
    else if (i4 < NX4 + 2 * NW4) { src = Wk; dst = g_wk; rel = i4 - NX4 - NW4; }
    else if (i4 < NX4 + 3 * NW4) { src = Wv; dst = g_wv; rel = i4 - NX4 - 2 * NW4; }
    else                         { src = Wo; dst = g_wo; rel = i4 - NX4 - 3 * NW4; }

    float4 v = ((const float4*)src)[rel];
    size_t e = rel * 4;
    uint32_t* p = dst + (e & ~(size_t)7);
    int off = (e & 4) ? 1 : 0;
    p[off + 0] = f2tf(v.x);
    p[off + 2] = f2tf(v.y);
    p[off + 4] = f2tf(v.z);
    p[off + 6] = f2tf(v.w);
}

// ---------------------------------------------------------------------------
// Shared GEMM mainloop: C(128x128) = A(row0.., k) * B(col0.., k)^T over K=1024.
// Both operands are tf32 bits, k-permuted, row stride 1024 words.
// 4-stage cp.async pipeline, BK=16, smem stride 24 words (conflict-free uint2).
// smem: A stages [4][128][24] then B stages [4][128][24] = 98304 B.
// ---------------------------------------------------------------------------
#define GEMM_SMEM 98304

__device__ __forceinline__ void gemm_mainloop(const uint32_t* __restrict__ Ag,
                                              const uint32_t* __restrict__ Bg,
                                              int row0, int col0,
                                              uint32_t* smw, uint32_t sbase,
                                              float acc[2][8][4]) {
    const int t    = threadIdx.x;
    const int lane = t & 31;
    const int wid  = t >> 5;
    const int wm   = wid & 3;
    const int wn   = wid >> 2;
    const int g    = lane >> 2;
    const int c    = lane & 3;
    const int r_ld  = t >> 2;            // 0..63
    const int cc4w  = (t & 3) << 2;      // word offset 0,4,8,12

    const uint32_t thr_off = (uint32_t)(r_ld * 24 + cc4w) * 4;  // bytes
    const uint32_t* pa0 = &Ag[(size_t)(row0 + r_ld) * D_IN + cc4w];
    const uint32_t* pb0 = &Bg[(size_t)(col0 + r_ld) * D_IN + cc4w];

#define G_ISSUE(kc)                                                        \
    {                                                                      \
        uint32_t da = sbase + (((kc) & 3) * 12288) + thr_off;              \
        uint32_t db = da + 49152;                                          \
        cp16(da,        pa0 + (kc) * 16);                                  \
        cp16(da + 6144, pa0 + (kc) * 16 + (size_t)64 * D_IN);              \
        cp16(db,        pb0 + (kc) * 16);                                  \
        cp16(db + 6144, pb0 + (kc) * 16 + (size_t)64 * D_IN);              \
        asm volatile("cp.async.commit_group;");                            \
    }

#define G_COMPUTE(kc)                                                      \
    {                                                                      \
        const uint32_t* SA = smw + (((kc) & 3) * 3072);                    \
        const uint32_t* SB = SA + 12288;                                   \
        _Pragma("unroll")                                                  \
        for (int ks = 0; ks < 16; ks += 8) {                               \
            uint2 aA[2], aB[2];                                            \
            _Pragma("unroll")                                              \
            for (int mi = 0; mi < 2; mi++) {                               \
                int r = wm * 32 + mi * 16 + g;                             \
                aA[mi] = *(const uint2*)&SA[r * 24 + ks + 2 * c];          \
                aB[mi] = *(const uint2*)&SA[(r + 8) * 24 + ks + 2 * c];    \
            }                                                              \
            _Pragma("unroll")                                              \
            for (int ni = 0; ni < 8; ni++) {                               \
                int n = wn * 64 + ni * 8 + g;                              \
                uint2 bb = *(const uint2*)&SB[n * 24 + ks + 2 * c];        \
                mma8(acc[0][ni], aA[0].x, aB[0].x, aA[0].y, aB[0].y, bb.x, bb.y); \
                mma8(acc[1][ni], aA[1].x, aB[1].x, aA[1].y, aB[1].y, bb.x, bb.y); \
            }                                                              \
        }                                                                  \
    }

#pragma unroll
    for (int mi = 0; mi < 2; mi++)
#pragma unroll
        for (int ni = 0; ni < 8; ni++)
#pragma unroll
            for (int j = 0; j < 4; j++) acc[mi][ni][j] = 0.f;

    G_ISSUE(0); G_ISSUE(1); G_ISSUE(2);

    for (int kc = 0; kc < 62; kc++) {
        asm volatile("cp.async.wait_group 2;");
        __syncthreads();
        G_COMPUTE(kc);
        if (kc + 3 < 64) G_ISSUE(kc + 3);
    }
    asm volatile("cp.async.wait_group 1;");
    __syncthreads();
    G_COMPUTE(62);
    asm volatile("cp.async.wait_group 0;");
    __syncthreads();
    G_COMPUTE(63);

#undef G_ISSUE
#undef G_COMPUTE
}

// ---------------------------------------------------------------------------
// QKV projection: out = x @ W^T. Q/K written hd-permuted, V plain, [B,H,S,hd].
// grid: (8, 32, 3), block 256.
// ---------------------------------------------------------------------------
__global__ __launch_bounds__(256, 2) void qkv_gemm() {
    extern __shared__ uint32_t smw[];
    const uint32_t sbase = (uint32_t)__cvta_generic_to_shared(smw);

    const uint32_t* W = (blockIdx.z == 0) ? g_wq : (blockIdx.z == 1) ? g_wk : g_wv;
    uint32_t*     out = (blockIdx.z == 0) ? g_q  : (blockIdx.z == 1) ? g_k  : g_v;
    const bool permout = (blockIdx.z != 2);

    const int row0 = blockIdx.y * 128;
    const int col0 = blockIdx.x * 128;

    float acc[2][8][4];
    gemm_mainloop(g_xt, W, row0, col0, smw, sbase, acc);

    const int t    = threadIdx.x;
    const int lane = t & 31;
    const int wid  = t >> 5;
    const int wm   = wid & 3;
    const int wn   = wid >> 2;
    const int g    = lane >> 2;
    const int c    = lane & 3;
    const int b    = row0 >> 11;

#pragma unroll
    for (int mi = 0; mi < 2; mi++) {
#pragma unroll
        for (int ni = 0; ni < 8; ni++) {
            int r = row0 + wm * 32 + mi * 16 + g;
            int f = col0 + wn * 64 + ni * 8 + 2 * c;
            int h = f >> 6;
            int d = f & 63;
            uint32_t v0 = f2tf(acc[mi][ni][0]);
            uint32_t v1 = f2tf(acc[mi][ni][1]);
            uint32_t v2 = f2tf(acc[mi][ni][2]);
            uint32_t v3 = f2tf(acc[mi][ni][3]);
            int s  = r & (SEQ - 1);
            int s2 = (r + 8) & (SEQ - 1);
            size_t baseA = (((size_t)(b * NHEAD + h) * SEQ + s)  << 6);
            size_t baseB = (((size_t)(b * NHEAD + h) * SEQ + s2) << 6);
            if (permout) {
                int gb = d & ~7;
                int e0 = d & 7;
                int p0 = gb + perm8(e0), p1 = gb + perm8(e0 + 1);
                out[baseA + p0] = v0; out[baseA + p1] = v1;
                out[baseB + p0] = v2; out[baseB + p1] = v3;
            } else {
                *(uint2*)&out[baseA + d] = make_uint2(v0, v1);
                *(uint2*)&out[baseB + d] = make_uint2(v2, v3);
            }
        }
    }
}

// ---------------------------------------------------------------------------
// Output projection: d_out = ctx @ Wo^T + bo (ctx/Wo both k-permuted tf32).
// grid: (8, 32), block 256.
// ---------------------------------------------------------------------------
__global__ __launch_bounds__(256, 2) void proj_gemm(const float* __restrict__ bo,
                                                    float* __restrict__ Cout) {
    extern __shared__ uint32_t smw[];
    const uint32_t sbase = (uint32_t)__cvta_generic_to_shared(smw);

    const int row0 = blockIdx.y * 128;
    const int col0 = blockIdx.x * 128;

    float acc[2][8][4];
    gemm_mainloop(g_ctx, g_wo, row0, col0, smw, sbase, acc);

    const int t    = threadIdx.x;
    const int lane = t & 31;
    const int wid  = t >> 5;
    const int wm   = wid & 3;
    const int wn   = wid >> 2;
    const int g    = lane >> 2;
    const int c    = lane & 3;

#pragma unroll
    for (int mi = 0; mi < 2; mi++) {
#pragma unroll
        for (int ni = 0; ni < 8; ni++) {
            int r = row0 + wm * 32 + mi * 16 + g;
            int f = col0 + wn * 64 + ni * 8 + 2 * c;
            float2 bb = make_float2(bo[f], bo[f + 1]);
            *(float2*)&Cout[(size_t)r * D_OUT + f] =
                make_float2(acc[mi][ni][0] + bb.x, acc[mi][ni][1] + bb.y);
            *(float2*)&Cout[(size_t)(r + 8) * D_OUT + f] =
                make_float2(acc[mi][ni][2] + bb.x, acc[mi][ni][3] + bb.y);
        }
    }
}

// ---------------------------------------------------------------------------
// Flash attention (causal), tf32 mma.sync, 128 q-rows per CTA (8 warps),
// cp.async double-buffered 64-row K/V tiles. Q/K hd-permuted in gmem.
// Smem (words): K0|V0|K1|V1 (64x72 each) | Ps (128x72).
// grid: (SEQ/128, NHEAD, BATCH), block 256.
// ---------------------------------------------------------------------------
#define AS 72
#define ATTN_SMEM ((4 * 64 + 128) * AS * 4)   // 110592 B

__global__ __launch_bounds__(256, 2) void attn_kernel() {
    extern __shared__ uint32_t smu[];
    uint32_t* Kb[2] = { smu,             smu + 2 * 64 * AS };
    uint32_t* Vb[2] = { smu + 64 * AS,   smu + 3 * 64 * AS };
    uint32_t* Ps    = smu + 4 * 64 * AS;   // 128 rows

    const int t    = threadIdx.x;
    const int lane = t & 31;
    const int w    = t >> 5;          // 0..7
    const int g    = lane >> 2;
    const int c    = lane & 3;

    const int m0 = blockIdx.x * 128;
    const int h  = blockIdx.y;
    const int b  = blockIdx.z;

    const size_t head_base = ((size_t)(b * NHEAD + h)) * SEQ * HDIM;
    const uint32_t* qb = g_q + head_base;
    const uint32_t* kb = g_k + head_base;
    const uint32_t* vb = g_v + head_base;

    // cp.async map: thread covers rows rl+16j (j=0..3), 16B column cl
    const int rl = t >> 4;            // 0..15
    const int cl = (t & 15) << 2;     // word col 0..60
    uint32_t kbase[2], vbase[2];
#pragma unroll
    for (int bf = 0; bf < 2; bf++) {
        kbase[bf] = (uint32_t)__cvta_generic_to_shared(&Kb[bf][rl * AS + cl]);
        vbase[bf] = (uint32_t)__cvta_generic_to_shared(&Vb[bf][rl * AS + cl]);
    }
    const size_t grow = (size_t)rl * HDIM + cl;

#define ISSUE_TILE(n0, bf)                                                  \
    {                                                                       \
        _Pragma("unroll")                                                   \
        for (int j = 0; j < 4; j++) {                                       \
            cp16(kbase[bf] + j * (16 * AS * 4),                             \
                 &kb[(size_t)(n0) * HDIM + grow + (size_t)j * 16 * HDIM]);  \
            cp16(vbase[bf] + j * (16 * AS * 4),                             \
                 &vb[(size_t)(n0) * HDIM + grow + (size_t)j * 16 * HDIM]);  \
        }                                                                   \
        asm volatile("cp.async.commit_group;");                             \
    }

    ISSUE_TILE(0, 0);   // overlap first K/V load with Q staging

    // Stage Q (128 rows) into Ps, lift fragments (hd is permuted -> uint2)
    for (int i = t; i < 2048; i += 256) {
        int r  = i >> 4;
        int cc = (i & 15) << 2;
        *(uint4*)&Ps[r * AS + cc] = *(const uint4*)&qb[(size_t)(m0 + r) * HDIM + cc];
    }
    __syncthreads();

    uint32_t qf[8][4];
    const int qrow = w * 16 + g;
#pragma unroll
    for (int ks = 0; ks < 8; ks++) {
        uint2 qa = *(const uint2*)&Ps[qrow * AS + ks * 8 + 2 * c];
        uint2 qc = *(const uint2*)&Ps[(qrow + 8) * AS + ks * 8 + 2 * c];
        qf[ks][0] = qa.x; qf[ks][1] = qc.x; qf[ks][2] = qa.y; qf[ks][3] = qc.y;
    }

    float o[8][4];
#pragma unroll
    for (int ni = 0; ni < 8; ni++)
#pragma unroll
        for (int j = 0; j < 4; j++) o[ni][j] = 0.f;
    float mr0 = -1e30f, mr1 = -1e30f, lr0 = 0.f, lr1 = 0.f;

    const int rowA = m0 + w * 16 + g;
    const int rowB = rowA + 8;
    const int lastrow = m0 + w * 16 + 15;
    const int NT = (m0 >> 6) + 2;

    for (int it = 0; it < NT; it++) {
        const int n0  = it << 6;
        const int cur = it & 1;
        if (it + 1 < NT) {
            ISSUE_TILE((it + 1) << 6, cur ^ 1);
            asm volatile("cp.async.wait_group 1;");
        } else {
            asm volatile("cp.async.wait_group 0;");
        }
        __syncthreads();

        if (n0 <= lastrow) {   // warp has at least one unmasked column
            const uint32_t* Ks = Kb[cur];
            const uint32_t* Vs = Vb[cur];

            // S = Q K^T  (16x64 per warp); K hd-permuted -> uint2 B frags
            float s[8][4];
#pragma unroll
            for (int ni = 0; ni < 8; ni++)
#pragma unroll
                for (int j = 0; j < 4; j++) s[ni][j] = 0.f;

#pragma unroll
            for (int ks = 0; ks < 8; ks++) {
#pragma unroll
                for (int ni = 0; ni < 8; ni++) {
                    uint2 bb = *(const uint2*)&Ks[(ni * 8 + g) * AS + ks * 8 + 2 * c];
                    mma8(s[ni], qf[ks][0], qf[ks][1], qf[ks][2], qf[ks][3], bb.x, bb.y);
                }
            }

            const bool needmask = (n0 + 63 > rowA);
#pragma unroll
            for (int ni = 0; ni < 8; ni++) {
#pragma unroll
                for (int j = 0; j < 4; j++) s[ni][j] *= 0.125f;
                if (needmask) {
                    int col = n0 + ni * 8 + 2 * c;
                    if (col     > rowA) s[ni][0] = -1e30f;
                    if (col + 1 > rowA) s[ni][1] = -1e30f;
                    if (col     > rowB) s[ni][2] = -1e30f;
                    if (col + 1 > rowB) s[ni][3] = -1e30f;
                }
            }

            // Online softmax (row pairs per thread, quad-reduce)
            float mx0 = -1e30f, mx1 = -1e30f;
#pragma unroll
            for (int ni = 0; ni < 8; ni++) {
                mx0 = fmaxf(mx0, fmaxf(s[ni][0], s[ni][1]));
                mx1 = fmaxf(mx1, fmaxf(s[ni][2], s[ni][3]));
            }
            mx0 = fmaxf(mx0, __shfl_xor_sync(0xffffffffu, mx0, 1));
            mx0 = fmaxf(mx0, __shfl_xor_sync(0xffffffffu, mx0, 2));
            mx1 = fmaxf(mx1, __shfl_xor_sync(0xffffffffu, mx1, 1));
            mx1 = fmaxf(mx1, __shfl_xor_sync(0xffffffffu, mx1, 2));

            float mn0 = fmaxf(mr0, mx0);
            float mn1 = fmaxf(mr1, mx1);
            float sum0 = 0.f, sum1 = 0.f;
#pragma unroll
            for (int ni = 0; ni < 8; ni++) {
                s[ni][0] = __expf(s[ni][0] - mn0); sum0 += s[ni][0];
                s[ni][1] = __expf(s[ni][1] - mn0); sum0 += s[ni][1];
                s[ni][2] = __expf(s[ni][2] - mn1); sum1 += s[ni][2];
                s[ni][3] = __expf(s[ni][3] - mn1); sum1 += s[ni][3];
            }
            sum0 += __shfl_xor_sync(0xffffffffu, sum0, 1);
            sum0 += __shfl_xor_sync(0xffffffffu, sum0, 2);
            sum1 += __shfl_xor_sync(0xffffffffu, sum1, 1);
            sum1 += __shfl_xor_sync(0xffffffffu, sum1, 2);

            float a0 = __expf(mr0 - mn0);
            float a1 = __expf(mr1 - mn1);
            lr0 = lr0 * a0 + sum0;
            lr1 = lr1 * a1 + sum1;
            mr0 = mn0; mr1 = mn1;
#pragma unroll
            for (int ni = 0; ni < 8; ni++) {
                o[ni][0] *= a0; o[ni][1] *= a0;
                o[ni][2] *= a1; o[ni][3] *= a1;
            }

            // P -> warp-private smem rows (tf32, plain k layout)
            int pr0 = qrow * AS;
#pragma unroll
            for (int ni = 0; ni < 8; ni++) {
                *(uint2*)&Ps[pr0 + ni * 8 + 2 * c] =
                    make_uint2(f2tf(s[ni][0]), f2tf(s[ni][1]));
                *(uint2*)&Ps[pr0 + 8 * AS + ni * 8 + 2 * c] =
                    make_uint2(f2tf(s[ni][2]), f2tf(s[ni][3]));
            }
            __syncwarp();

            // O += P V  (V plain)
#pragma unroll
            for (int ks = 0; ks < 8; ks++) {
                int base = qrow * AS + ks * 8;
                uint32_t a0f = Ps[base + c];
                uint32_t a1f = Ps[base + 8 * AS + c];
                uint32_t a2f = Ps[base + c + 4];
                uint32_t a3f = Ps[base + 8 * AS + c + 4];
#pragma unroll
                for (int ni = 0; ni < 8; ni++) {
                    uint32_t b0 = Vs[(ks * 8 + c) * AS + ni * 8 + g];
                    uint32_t b1 = Vs[(ks * 8 + c + 4) * AS + ni * 8 + g];
                    mma8(o[ni], a0f, a1f, a2f, a3f, b0, b1);
                }
            }
        }
        __syncthreads();   // buffer 'cur' free for next prefetch
    }
#undef ISSUE_TILE

    // Epilogue: normalize, write ctx feature-PERMUTED tf32 (proj consumes it)
    float inv0 = 1.f / lr0;
    float inv1 = 1.f / lr1;
    const size_t rA = ((size_t)(b * SEQ + rowA)) * D_OUT + h * HDIM;
    const size_t rB = ((size_t)(b * SEQ + rowB)) * D_OUT + h * HDIM;
#pragma unroll
    for (int ni = 0; ni < 8; ni++) {
        int e0 = ni * 8 + 2 * c;
        int gb = e0 & ~7;
        int p0 = gb + perm8(e0 & 7);
        int p1 = gb + perm8((e0 & 7) + 1);
        g_ctx[rA + p0] = f2tf(o[ni][0] * inv0);
        g_ctx[rA + p1] = f2tf(o[ni][1] * inv0);
        g_ctx[rB + p0] = f2tf(o[ni][2] * inv1);
        g_ctx[rB + p1] = f2tf(o[ni][3] * inv1);
    }
}

// ---------------------------------------------------------------------------
extern "C" void kernel_launch(void* const* d_in, const int* in_sizes, int n_in,
                              void* d_out, int out_size) {
    const float* x  = (const float*)d_in[0];
    const float* Wq = (const float*)d_in[1];
    const float* Wk = (const float*)d_in[2];
    const float* Wv = (const float*)d_in[3];
    const float* Wo = (const float*)d_in[4];
    const float* bo = (const float*)d_in[5];
    float* out = (float*)d_out;

    cudaFuncSetAttribute(qkv_gemm,
                         cudaFuncAttributeMaxDynamicSharedMemorySize, GEMM_SMEM);
    cudaFuncSetAttribute(proj_gemm,
                         cudaFuncAttributeMaxDynamicSharedMemorySize, GEMM_SMEM);
    cudaFuncSetAttribute(attn_kernel,
                         cudaFuncAttributeMaxDynamicSharedMemorySize, ATTN_SMEM);

    prep_kernel<<<8192, 256>>>(x, Wq, Wk, Wv, Wo);
    qkv_gemm<<<dim3(D_OUT / 128, NTOK / 128, 3), 256, GEMM_SMEM>>>();
    attn_kernel<<<dim3(SEQ / 128, NHEAD, BATCH), 256, ATTN_SMEM>>>();
    proj_gemm<<<dim3(D_OUT / 128, NTOK / 128), 256, GEMM_SMEM>>>(bo, out);
}

// round 8
// speedup vs baseline: 3.4865x; 1.0429x over previous
#include <cuda_runtime.h>
#include <math.h>
#include <stdint.h>

#define D_IN   1024
#define D_OUT  1024
#define SEQ    2048
#define BATCH  2
#define NHEAD  16
#define HDIM   64
#define NTOK   (BATCH * SEQ)   // 4096

// Scratch (tf32 bit patterns). Q/K permuted along hd; V plain; ctx permuted
// along features; x/weights permuted along their k dim.
__device__ uint32_t g_q[NTOK * D_OUT];
__device__ uint32_t g_k[NTOK * D_OUT];
__device__ uint32_t g_v[NTOK * D_OUT];
__device__ uint32_t g_ctx[NTOK * D_OUT];
__device__ uint32_t g_xt[NTOK * D_IN];
__device__ uint32_t g_wq[D_OUT * D_IN];
__device__ uint32_t g_wk[D_OUT * D_IN];
__device__ uint32_t g_wv[D_OUT * D_IN];
__device__ uint32_t g_wo[D_OUT * D_IN];

__device__ __forceinline__ uint32_t f2tf(float x) {
    uint32_t u;
    asm("cvt.rna.tf32.f32 %0, %1;" : "=r"(u) : "f"(x));
    return u;
}

// k-permutation within groups of 8: k -> 2*(k&3) + (k>>2)
__device__ __forceinline__ int perm8(int e) { return ((e & 3) << 1) | ((e >> 2) & 1); }

__device__ __forceinline__ void mma8(float c[4],
                                     uint32_t a0, uint32_t a1, uint32_t a2, uint32_t a3,
                                     uint32_t b0, uint32_t b1) {
    asm volatile(
        "mma.sync.aligned.m16n8k8.row.col.f32.tf32.tf32.f32 "
        "{%0,%1,%2,%3},{%4,%5,%6,%7},{%8,%9},{%0,%1,%2,%3};"
        : "+f"(c[0]), "+f"(c[1]), "+f"(c[2]), "+f"(c[3])
        : "r"(a0), "r"(a1), "r"(a2), "r"(a3), "r"(b0), "r"(b1));
}

__device__ __forceinline__ void cp16(uint32_t dst_smem, const void* src) {
    asm volatile("cp.async.cg.shared.global [%0], [%1], 16;\n"
                 :: "r"(dst_smem), "l"(src));
}

// ---------------------------------------------------------------------------
// prep: convert x + 4 weight matrices to tf32 bits with k-permuted layout.
// ---------------------------------------------------------------------------
__global__ __launch_bounds__(256) void prep_kernel(const float* __restrict__ x,
                                                   const float* __restrict__ Wq,
                                                   const float* __restrict__ Wk,
                                                   const float* __restrict__ Wv,
                                                   const float* __restrict__ Wo) {
    const size_t NX4 = (size_t)NTOK * D_IN / 4;      // 1048576
    const size_t NW4 = (size_t)D_OUT * D_IN / 4;     // 262144
    size_t i4 = (size_t)blockIdx.x * 256 + threadIdx.x;

    const float* src;
    uint32_t* dst;
    size_t rel;
    if (i4 < NX4)                { src = x;  dst = g_xt; rel = i4; }
    else if (i4 < NX4 + NW4)     { src = Wq; dst = g_wq; rel = i4 - NX4; }
    else if (i4 < NX4 + 2 * NW4) { src = Wk; dst = g_wk; rel = i4 - NX4 - NW4; }
    else if (i4 < NX4 + 3 * NW4) { src = Wv; dst = g_wv; rel = i4 - NX4 - 2 * NW4; }
    else                         { src = Wo; dst = g_wo; rel = i4 - NX4 - 3 * NW4; }

    float4 v = ((const float4*)src)[rel];
    size_t e = rel * 4;
    uint32_t* p = dst + (e & ~(size_t)7);
    int off = (e & 4) ? 1 : 0;
    p[off + 0] = f2tf(v.x);
    p[off + 2] = f2tf(v.y);
    p[off + 4] = f2tf(v.z);
    p[off + 6] = f2tf(v.w);
}

// ---------------------------------------------------------------------------
// GEMM mainloop: C(128x128) = A(row0..,k) * B(col0..,k)^T over K=1024.
// 128 threads, 4 warps (2x2), 64x64 warp tiles (mi=4). BK=16, 4-stage
// cp.async, k-permuted operands, smem stride 24 words (conflict-free uint2).
// smem: A stages [4][128][24] | B stages [4][128][24] = 98304 B.
// ---------------------------------------------------------------------------
#define GEMM_SMEM 98304

__device__ __forceinline__ void gemm_mainloop(const uint32_t* __restrict__ Ag,
                                              const uint32_t* __restrict__ Bg,
                                              int row0, int col0,
                                              uint32_t* smw, uint32_t sbase,
                                              float acc[4][8][4]) {
    const int t    = threadIdx.x;
    const int lane = t & 31;
    const int wid  = t >> 5;
    const int wm   = wid & 1;
    const int wn   = wid >> 1;
    const int g    = lane >> 2;
    const int c    = lane & 3;

    const int r0l  = t >> 2;             // 0..31, rows r0l + 32*i
    const int cw0  = (t & 3) << 2;       // word col 0,4,8,12
    const uint32_t soff0 = (uint32_t)(r0l * 24 + cw0) * 4;
    const uint32_t* pa = &Ag[(size_t)(row0 + r0l) * D_IN + cw0];
    const uint32_t* pb = &Bg[(size_t)(col0 + r0l) * D_IN + cw0];

#define G_ISSUE(kc)                                                        \
    {                                                                      \
        uint32_t da = sbase + (((kc) & 3) * 12288) + soff0;                \
        uint32_t db = da + 49152;                                          \
        _Pragma("unroll")                                                  \
        for (int i = 0; i < 4; i++) {                                      \
            cp16(da + i * 3072, pa + (kc) * 16 + (size_t)(32 * i) * D_IN); \
            cp16(db + i * 3072, pb + (kc) * 16 + (size_t)(32 * i) * D_IN); \
        }                                                                  \
        asm volatile("cp.async.commit_group;");                            \
    }

#define G_COMPUTE(kc)                                                      \
    {                                                                      \
        const uint32_t* SA = smw + (((kc) & 3) * 3072);                    \
        const uint32_t* SB = SA + 12288;                                   \
        _Pragma("unroll")                                                  \
        for (int ks = 0; ks < 16; ks += 8) {                               \
            uint2 aA[4], aB[4];                                            \
            _Pragma("unroll")                                              \
            for (int mi = 0; mi < 4; mi++) {                               \
                int r = wm * 64 + mi * 16 + g;                             \
                aA[mi] = *(const uint2*)&SA[r * 24 + ks + 2 * c];          \
                aB[mi] = *(const uint2*)&SA[(r + 8) * 24 + ks + 2 * c];    \
            }                                                              \
            _Pragma("unroll")                                              \
            for (int ni = 0; ni < 8; ni++) {                               \
                int n = wn * 64 + ni * 8 + g;                              \
                uint2 bb = *(const uint2*)&SB[n * 24 + ks + 2 * c];        \
                _Pragma("unroll")                                          \
                for (int mi = 0; mi < 4; mi++)                             \
                    mma8(acc[mi][ni], aA[mi].x, aB[mi].x, aA[mi].y, aB[mi].y, bb.x, bb.y); \
            }                                                              \
        }                                                                  \
    }

#pragma unroll
    for (int mi = 0; mi < 4; mi++)
#pragma unroll
        for (int ni = 0; ni < 8; ni++)
#pragma unroll
            for (int j = 0; j < 4; j++) acc[mi][ni][j] = 0.f;

    G_ISSUE(0); G_ISSUE(1); G_ISSUE(2);

    for (int kc = 0; kc < 62; kc++) {
        asm volatile("cp.async.wait_group 2;");
        __syncthreads();
        G_COMPUTE(kc);
        if (kc + 3 < 64) G_ISSUE(kc + 3);
    }
    asm volatile("cp.async.wait_group 1;");
    __syncthreads();
    G_COMPUTE(62);
    asm volatile("cp.async.wait_group 0;");
    __syncthreads();
    G_COMPUTE(63);

#undef G_ISSUE
#undef G_COMPUTE
}

// ---------------------------------------------------------------------------
// QKV projection: out = x @ W^T. Q/K written hd-permuted, V plain, [B,H,S,hd].
// grid: (8, 32, 3), block 128.
// ---------------------------------------------------------------------------
__global__ __launch_bounds__(128, 2) void qkv_gemm() {
    extern __shared__ uint32_t smw[];
    const uint32_t sbase = (uint32_t)__cvta_generic_to_shared(smw);

    const uint32_t* W = (blockIdx.z == 0) ? g_wq : (blockIdx.z == 1) ? g_wk : g_wv;
    uint32_t*     out = (blockIdx.z == 0) ? g_q  : (blockIdx.z == 1) ? g_k  : g_v;
    const bool permout = (blockIdx.z != 2);

    const int row0 = blockIdx.y * 128;
    const int col0 = blockIdx.x * 128;

    float acc[4][8][4];
    gemm_mainloop(g_xt, W, row0, col0, smw, sbase, acc);

    const int t    = threadIdx.x;
    const int lane = t & 31;
    const int wid  = t >> 5;
    const int wm   = wid & 1;
    const int wn   = wid >> 1;
    const int g    = lane >> 2;
    const int c    = lane & 3;
    const int b    = row0 >> 11;

#pragma unroll
    for (int mi = 0; mi < 4; mi++) {
#pragma unroll
        for (int ni = 0; ni < 8; ni++) {
            int r = row0 + wm * 64 + mi * 16 + g;
            int f = col0 + wn * 64 + ni * 8 + 2 * c;
            int h = f >> 6;
            int d = f & 63;
            uint32_t v0 = f2tf(acc[mi][ni][0]);
            uint32_t v1 = f2tf(acc[mi][ni][1]);
            uint32_t v2 = f2tf(acc[mi][ni][2]);
            uint32_t v3 = f2tf(acc[mi][ni][3]);
            int s  = r & (SEQ - 1);
            int s2 = (r + 8) & (SEQ - 1);
            size_t baseA = (((size_t)(b * NHEAD + h) * SEQ + s)  << 6);
            size_t baseB = (((size_t)(b * NHEAD + h) * SEQ + s2) << 6);
            if (permout) {
                int gb = d & ~7;
                int e0 = d & 7;
                int p0 = gb + perm8(e0), p1 = gb + perm8(e0 + 1);
                out[baseA + p0] = v0; out[baseA + p1] = v1;
                out[baseB + p0] = v2; out[baseB + p1] = v3;
            } else {
                *(uint2*)&out[baseA + d] = make_uint2(v0, v1);
                *(uint2*)&out[baseB + d] = make_uint2(v2, v3);
            }
        }
    }
}

// ---------------------------------------------------------------------------
// Output projection: d_out = ctx @ Wo^T + bo (ctx/Wo both k-permuted tf32).
// grid: (8, 32), block 128.
// ---------------------------------------------------------------------------
__global__ __launch_bounds__(128, 2) void proj_gemm(const float* __restrict__ bo,
                                                    float* __restrict__ Cout) {
    extern __shared__ uint32_t smw[];
    const uint32_t sbase = (uint32_t)__cvta_generic_to_shared(smw);

    const int row0 = blockIdx.y * 128;
    const int col0 = blockIdx.x * 128;

    float acc[4][8][4];
    gemm_mainloop(g_ctx, g_wo, row0, col0, smw, sbase, acc);

    const int t    = threadIdx.x;
    const int lane = t & 31;
    const int wid  = t >> 5;
    const int wm   = wid & 1;
    const int wn   = wid >> 1;
    const int g    = lane >> 2;
    const int c    = lane & 3;

#pragma unroll
    for (int mi = 0; mi < 4; mi++) {
#pragma unroll
        for (int ni = 0; ni < 8; ni++) {
            int r = row0 + wm * 64 + mi * 16 + g;
            int f = col0 + wn * 64 + ni * 8 + 2 * c;
            float2 bb = make_float2(bo[f], bo[f + 1]);
            *(float2*)&Cout[(size_t)r * D_OUT + f] =
                make_float2(acc[mi][ni][0] + bb.x, acc[mi][ni][1] + bb.y);
            *(float2*)&Cout[(size_t)(r + 8) * D_OUT + f] =
                make_float2(acc[mi][ni][2] + bb.x, acc[mi][ni][3] + bb.y);
        }
    }
}

// ---------------------------------------------------------------------------
// Flash attention (causal), tf32 mma.sync. 128 q-rows per CTA, 4 warps of
// 32 q-rows each (mi=2), cp.async double-buffered 64-row K/V tiles.
// Smem (words): K0|V0|K1|V1 (64x72 each) | Ps (128x72).
// grid: (SEQ/128, NHEAD, BATCH), block 128.
// ---------------------------------------------------------------------------
#define AS 72
#define ATTN_SMEM ((4 * 64 + 128) * AS * 4)   // 110592 B

__global__ __launch_bounds__(128, 2) void attn_kernel() {
    extern __shared__ uint32_t smu[];
    uint32_t* Kb[2] = { smu,             smu + 2 * 64 * AS };
    uint32_t* Vb[2] = { smu + 64 * AS,   smu + 3 * 64 * AS };
    uint32_t* Ps    = smu + 4 * 64 * AS;   // 128 rows

    const int t    = threadIdx.x;
    const int lane = t & 31;
    const int w    = t >> 5;          // 0..3
    const int g    = lane >> 2;
    const int c    = lane & 3;

    const int m0 = blockIdx.x * 128;
    const int h  = blockIdx.y;
    const int b  = blockIdx.z;

    const size_t head_base = ((size_t)(b * NHEAD + h)) * SEQ * HDIM;
    const uint32_t* qb = g_q + head_base;
    const uint32_t* kb = g_k + head_base;
    const uint32_t* vb = g_v + head_base;

    // cp.async map: thread covers rows rl+8j (j=0..7), 16B column cl
    const int rl = t >> 4;            // 0..7
    const int cl = (t & 15) << 2;     // word col 0..60
    uint32_t kbase[2], vbase[2];
#pragma unroll
    for (int bf = 0; bf < 2; bf++) {
        kbase[bf] = (uint32_t)__cvta_generic_to_shared(&Kb[bf][rl * AS + cl]);
        vbase[bf] = (uint32_t)__cvta_generic_to_shared(&Vb[bf][rl * AS + cl]);
    }
    const size_t grow = (size_t)rl * HDIM + cl;

#define ISSUE_TILE(n0, bf)                                                  \
    {                                                                       \
        _Pragma("unroll")                                                   \
        for (int j = 0; j < 8; j++) {                                       \
            cp16(kbase[bf] + j * (8 * AS * 4),                              \
                 &kb[(size_t)(n0) * HDIM + grow + (size_t)j * 8 * HDIM]);   \
            cp16(vbase[bf] + j * (8 * AS * 4),                              \
                 &vb[(size_t)(n0) * HDIM + grow + (size_t)j * 8 * HDIM]);   \
        }                                                                   \
        asm volatile("cp.async.commit_group;");                             \
    }

    ISSUE_TILE(0, 0);   // overlap first K/V load with Q staging

    // Stage Q (128 rows) into Ps, lift fragments (hd permuted -> uint2)
    for (int i = t; i < 2048; i += 128) {
        int r  = i >> 4;
        int cc = (i & 15) << 2;
        *(uint4*)&Ps[r * AS + cc] = *(const uint4*)&qb[(size_t)(m0 + r) * HDIM + cc];
    }
    __syncthreads();

    uint32_t qf[8][2][4];
#pragma unroll
    for (int ks = 0; ks < 8; ks++) {
#pragma unroll
        for (int mi = 0; mi < 2; mi++) {
            int row = w * 32 + mi * 16 + g;
            uint2 qa = *(const uint2*)&Ps[row * AS + ks * 8 + 2 * c];
            uint2 qc = *(const uint2*)&Ps[(row + 8) * AS + ks * 8 + 2 * c];
            qf[ks][mi][0] = qa.x; qf[ks][mi][1] = qc.x;
            qf[ks][mi][2] = qa.y; qf[ks][mi][3] = qc.y;
        }
    }

    float o[2][8][4];
#pragma unroll
    for (int mi = 0; mi < 2; mi++)
#pragma unroll
        for (int ni = 0; ni < 8; ni++)
#pragma unroll
            for (int j = 0; j < 4; j++) o[mi][ni][j] = 0.f;
    float mr[2][2], lr[2][2];
#pragma unroll
    for (int mi = 0; mi < 2; mi++) {
        mr[mi][0] = -1e30f; mr[mi][1] = -1e30f;
        lr[mi][0] = 0.f;    lr[mi][1] = 0.f;
    }

    int rA[2], rB[2];
#pragma unroll
    for (int mi = 0; mi < 2; mi++) {
        rA[mi] = m0 + w * 32 + mi * 16 + g;
        rB[mi] = rA[mi] + 8;
    }
    const int lastrow = m0 + w * 32 + 31;
    const int NT = (m0 >> 6) + 2;

    for (int it = 0; it < NT; it++) {
        const int n0  = it << 6;
        const int cur = it & 1;
        if (it + 1 < NT) {
            ISSUE_TILE((it + 1) << 6, cur ^ 1);
            asm volatile("cp.async.wait_group 1;");
        } else {
            asm volatile("cp.async.wait_group 0;");
        }
        __syncthreads();

        if (n0 <= lastrow) {   // warp has at least one unmasked column
            const uint32_t* Ks = Kb[cur];
            const uint32_t* Vs = Vb[cur];

            // S = Q K^T  (32x64 per warp, 2 x m16)
            float s[2][8][4];
#pragma unroll
            for (int mi = 0; mi < 2; mi++)
#pragma unroll
                for (int ni = 0; ni < 8; ni++)
#pragma unroll
                    for (int j = 0; j < 4; j++) s[mi][ni][j] = 0.f;

#pragma unroll
            for (int ks = 0; ks < 8; ks++) {
#pragma unroll
                for (int ni = 0; ni < 8; ni++) {
                    uint2 bb = *(const uint2*)&Ks[(ni * 8 + g) * AS + ks * 8 + 2 * c];
#pragma unroll
                    for (int mi = 0; mi < 2; mi++)
                        mma8(s[mi][ni], qf[ks][mi][0], qf[ks][mi][1],
                             qf[ks][mi][2], qf[ks][mi][3], bb.x, bb.y);
                }
            }

#pragma unroll
            for (int mi = 0; mi < 2; mi++) {
                const bool needmask = (n0 + 63 > rA[mi]);
#pragma unroll
                for (int ni = 0; ni < 8; ni++) {
#pragma unroll
                    for (int j = 0; j < 4; j++) s[mi][ni][j] *= 0.125f;
                    if (needmask) {
                        int col = n0 + ni * 8 + 2 * c;
                        if (col     > rA[mi]) s[mi][ni][0] = -1e30f;
                        if (col + 1 > rA[mi]) s[mi][ni][1] = -1e30f;
                        if (col     > rB[mi]) s[mi][ni][2] = -1e30f;
                        if (col + 1 > rB[mi]) s[mi][ni][3] = -1e30f;
                    }
                }
            }

            // Online softmax per mi (two rows per thread, quad-reduce)
#pragma unroll
            for (int mi = 0; mi < 2; mi++) {
                float mx0 = -1e30f, mx1 = -1e30f;
#pragma unroll
                for (int ni = 0; ni < 8; ni++) {
                    mx0 = fmaxf(mx0, fmaxf(s[mi][ni][0], s[mi][ni][1]));
                    mx1 = fmaxf(mx1, fmaxf(s[mi][ni][2], s[mi][ni][3]));
                }
                mx0 = fmaxf(mx0, __shfl_xor_sync(0xffffffffu, mx0, 1));
                mx0 = fmaxf(mx0, __shfl_xor_sync(0xffffffffu, mx0, 2));
                mx1 = fmaxf(mx1, __shfl_xor_sync(0xffffffffu, mx1, 1));
                mx1 = fmaxf(mx1, __shfl_xor_sync(0xffffffffu, mx1, 2));

                float mn0 = fmaxf(mr[mi][0], mx0);
                float mn1 = fmaxf(mr[mi][1], mx1);
                float sum0 = 0.f, sum1 = 0.f;
#pragma unroll
                for (int ni = 0; ni < 8; ni++) {
                    s[mi][ni][0] = __expf(s[mi][ni][0] - mn0); sum0 += s[mi][ni][0];
                    s[mi][ni][1] = __expf(s[mi][ni][1] - mn0); sum0 += s[mi][ni][1];
                    s[mi][ni][2] = __expf(s[mi][ni][2] - mn1); sum1 += s[mi][ni][2];
                    s[mi][ni][3] = __expf(s[mi][ni][3] - mn1); sum1 += s[mi][ni][3];
                }
                sum0 += __shfl_xor_sync(0xffffffffu, sum0, 1);
                sum0 += __shfl_xor_sync(0xffffffffu, sum0, 2);
                sum1 += __shfl_xor_sync(0xffffffffu, sum1, 1);
                sum1 += __shfl_xor_sync(0xffffffffu, sum1, 2);

                float a0 = __expf(mr[mi][0] - mn0);
                float a1 = __expf(mr[mi][1] - mn1);
                lr[mi][0] = lr[mi][0] * a0 + sum0;
                lr[mi][1] = lr[mi][1] * a1 + sum1;
                mr[mi][0] = mn0; mr[mi][1] = mn1;
#pragma unroll
                for (int ni = 0; ni < 8; ni++) {
                    o[mi][ni][0] *= a0; o[mi][ni][1] *= a0;
                    o[mi][ni][2] *= a1; o[mi][ni][3] *= a1;
                }

                // P -> warp-private smem rows (tf32, plain k layout)
                int pr0 = (w * 32 + mi * 16 + g) * AS;
#pragma unroll
                for (int ni = 0; ni < 8; ni++) {
                    *(uint2*)&Ps[pr0 + ni * 8 + 2 * c] =
                        make_uint2(f2tf(s[mi][ni][0]), f2tf(s[mi][ni][1]));
                    *(uint2*)&Ps[pr0 + 8 * AS + ni * 8 + 2 * c] =
                        make_uint2(f2tf(s[mi][ni][2]), f2tf(s[mi][ni][3]));
                }
            }
            __syncwarp();

            // O += P V  (V plain; B frags shared across mi)
#pragma unroll
            for (int ks = 0; ks < 8; ks++) {
                uint32_t af[2][4];
#pragma unroll
                for (int mi = 0; mi < 2; mi++) {
                    int base = (w * 32 + mi * 16 + g) * AS + ks * 8;
                    af[mi][0] = Ps[base + c];
                    af[mi][1] = Ps[base + 8 * AS + c];
                    af[mi][2] = Ps[base + c + 4];
                    af[mi][3] = Ps[base + 8 * AS + c + 4];
                }
#pragma unroll
                for (int ni = 0; ni < 8; ni++) {
                    uint32_t b0 = Vs[(ks * 8 + c) * AS + ni * 8 + g];
                    uint32_t b1 = Vs[(ks * 8 + c + 4) * AS + ni * 8 + g];
#pragma unroll
                    for (int mi = 0; mi < 2; mi++)
                        mma8(o[mi][ni], af[mi][0], af[mi][1], af[mi][2], af[mi][3], b0, b1);
                }
            }
        }
        __syncthreads();   // buffer 'cur' free for next prefetch
    }
#undef ISSUE_TILE

    // Epilogue: normalize, write ctx feature-PERMUTED tf32 (proj consumes it)
#pragma unroll
    for (int mi = 0; mi < 2; mi++) {
        float inv0 = 1.f / lr[mi][0];
        float inv1 = 1.f / lr[mi][1];
        const size_t pA = ((size_t)(b * SEQ + rA[mi])) * D_OUT + h * HDIM;
        const size_t pB = ((size_t)(b * SEQ + rB[mi])) * D_OUT + h * HDIM;
#pragma unroll
        for (int ni = 0; ni < 8; ni++) {
            int e0 = ni * 8 + 2 * c;
            int gb = e0 & ~7;
            int p0 = gb + perm8(e0 & 7);
            int p1 = gb + perm8((e0 & 7) + 1);
            g_ctx[pA + p0] = f2tf(o[mi][ni][0] * inv0);
            g_ctx[pA + p1] = f2tf(o[mi][ni][1] * inv0);
            g_ctx[pB + p0] = f2tf(o[mi][ni][2] * inv1);
            g_ctx[pB + p1] = f2tf(o[mi][ni][3] * inv1);
        }
    }
}

// ---------------------------------------------------------------------------
extern "C" void kernel_launch(void* const* d_in, const int* in_sizes, int n_in,
                              void* d_out, int out_size) {
    const float* x  = (const float*)d_in[0];
    const float* Wq = (const float*)d_in[1];
    const float* Wk = (const float*)d_in[2];
    const float* Wv = (const float*)d_in[3];
    const float* Wo = (const float*)d_in[4];
    const float* bo = (const float*)d_in[5];
    float* out = (float*)d_out;

    cudaFuncSetAttribute(qkv_gemm,
                         cudaFuncAttributeMaxDynamicSharedMemorySize, GEMM_SMEM);
    cudaFuncSetAttribute(proj_gemm,
                         cudaFuncAttributeMaxDynamicSharedMemorySize, GEMM_SMEM);
    cudaFuncSetAttribute(attn_kernel,
                         cudaFuncAttributeMaxDynamicSharedMemorySize, ATTN_SMEM);

    prep_kernel<<<8192, 256>>>(x, Wq, Wk, Wv, Wo);
    qkv_gemm<<<dim3(D_OUT / 128, NTOK / 128, 3), 128, GEMM_SMEM>>>();
    attn_kernel<<<dim3(SEQ / 128, NHEAD, BATCH), 128, ATTN_SMEM>>>();
    proj_gemm<<<dim3(D_OUT / 128, NTOK / 128), 128, GEMM_SMEM>>>(bo, out);
}